// round 11
// baseline (speedup 1.0000x reference)
#include <cuda_runtime.h>
#include <cuda_bf16.h>
#include <math.h>
#include <float.h>

#define D 64
#define L 64
#define DIMF 512
#define G 256
#define M 192                 // 3*L nodes (= hyperedges) per dialogue
#define KTOP 12
#define NROWS 4096            // D*L
#define NNODE (D*M)           // 12288
#define TAUINV (1.0f/0.07f)
#define SQTAUI 3.7796447300922722f   // sqrt(1/0.07)

// ---- scratch (static device arrays; no allocation allowed) ----
__device__ float    g_sq[NNODE];
__device__ unsigned g_fh[(size_t)NNODE*DIMF];   // tf32 hi of features
__device__ unsigned g_fl[(size_t)NNODE*DIMF];   // tf32 lo of features
__device__ unsigned g_H[NNODE*6];       // 192-bit incidence mask per edge
__device__ float    g_X[NNODE*G];
__device__ float    g_Y[NNODE*G];
__device__ float    g_diag[3*NROWS];
__device__ float    g_rowsum[3*NROWS];
__device__ float    g_colsum[3*NROWS];
__device__ __nv_bfloat16 g_nb[(size_t)3*NROWS*G];   // normalized bf16 features (loss path only)

__device__ __forceinline__ const float* feat_row(int d, int n,
        const float* t, const float* a, const float* v) {
    int mod = n >> 6, i = n & 63;
    const float* base = (mod == 0) ? t : (mod == 1) ? a : v;
    return base + (size_t)(d * L + i) * DIMF;
}

// ---- tf32 helpers ----
__device__ __forceinline__ unsigned f2tf(float x) {
    unsigned u; asm("cvt.rna.tf32.f32 %0, %1;" : "=r"(u) : "f"(x)); return u;
}
__device__ __forceinline__ void hilo(float x, unsigned& h, unsigned& l) {
    h = f2tf(x);
    l = f2tf(x - __uint_as_float(h));
}
__device__ __forceinline__ void mma8(float* c, const unsigned* a, const unsigned* b) {
    asm volatile("mma.sync.aligned.m16n8k8.row.col.f32.tf32.tf32.f32 "
        "{%0,%1,%2,%3},{%4,%5,%6,%7},{%8,%9},{%0,%1,%2,%3};"
        : "+f"(c[0]), "+f"(c[1]), "+f"(c[2]), "+f"(c[3])
        : "r"(a[0]), "r"(a[1]), "r"(a[2]), "r"(a[3]), "r"(b[0]), "r"(b[1]));
}

// ---- cp.async helpers ----
__device__ __forceinline__ void cp16(void* dst_smem, const void* src) {
    unsigned ad = (unsigned)__cvta_generic_to_shared(dst_smem);
    asm volatile("cp.async.cg.shared.global [%0],[%1],16;" :: "r"(ad), "l"(src));
}
__device__ __forceinline__ void cp_commit() {
    asm volatile("cp.async.commit_group;");
}

// ---------------- K1: per-node squared norms + hi/lo precompute ----------------
__global__ void k_sq(const float* t, const float* a, const float* v) {
    int warp = (blockIdx.x * blockDim.x + threadIdx.x) >> 5;
    int lane = threadIdx.x & 31;
    if (warp >= NNODE) return;
    int d = warp / M, n = warp % M;
    const float* r = feat_row(d, n, t, a, v);
    float s = 0.f;
    #pragma unroll
    for (int c = lane; c < DIMF; c += 32) { float x = r[c]; s += x * x; }
    unsigned* fh = g_fh + (size_t)warp * DIMF;
    unsigned* fl = g_fl + (size_t)warp * DIMF;
    #pragma unroll
    for (int c0 = lane * 4; c0 < DIMF; c0 += 128) {
        float4 x = *(const float4*)(r + c0);
        uint4 h, l;
        hilo(x.x, h.x, l.x); hilo(x.y, h.y, l.y);
        hilo(x.z, h.z, l.z); hilo(x.w, h.w, l.w);
        *(uint4*)(fh + c0) = h;
        *(uint4*)(fl + c0) = l;
    }
    #pragma unroll
    for (int o = 16; o; o >>= 1) s += __shfl_down_sync(0xffffffffu, s, o);
    if (lane == 0) g_sq[warp] = s;
}

// ---------------- K2: 3xTF32 gram (64 rows/block) + d2 + top-12 + masks ----------------
#define GBP2 20
__global__ void __launch_bounds__(256) k_gram_mma() {
    __shared__ unsigned Bbuf[2 * 192 * GBP2];        // hi | lo ; reused as d2 [32][192]
    __shared__ float sq[M];
    unsigned* Bhi = Bbuf;
    unsigned* Blo = Bbuf + 192 * GBP2;

    int d = blockIdx.y, i0 = blockIdx.x * 64;
    int tid = threadIdx.x, lane = tid & 31, warp = tid >> 5;
    int gq = lane >> 2, tq = lane & 3;
    if (tid < M) sq[tid] = g_sq[d * M + tid];
    size_t base = (size_t)(d * M) * DIMF;

    float acc[4][3][4];
    #pragma unroll
    for (int mi = 0; mi < 4; mi++)
        #pragma unroll
        for (int ni = 0; ni < 3; ni++)
            #pragma unroll
            for (int e = 0; e < 4; e++) acc[mi][ni][e] = 0.f;

    for (int kc = 0; kc < DIMF; kc += 16) {
        #pragma unroll
        for (int it = 0; it < 3; it++) {
            int idx = tid + it * 256;              // 0..767
            int n = idx >> 2, k4 = (idx & 3) * 4;
            cp16(Bhi + n * GBP2 + k4, g_fh + base + (size_t)n * DIMF + kc + k4);
            cp16(Blo + n * GBP2 + k4, g_fl + base + (size_t)n * DIMF + kc + k4);
        }
        cp_commit();
        asm volatile("cp.async.wait_group 0;");
        __syncthreads();
        #pragma unroll
        for (int k0 = 0; k0 < 16; k0 += 8) {
            unsigned ah[4][4], al[4][4], bh[3][2], bl[3][2];
            #pragma unroll
            for (int mi = 0; mi < 4; mi++) {
                int r0 = (i0 + mi * 16 + gq) * GBP2;
                int r1 = r0 + 8 * GBP2;
                ah[mi][0] = Bhi[r0 + k0 + tq];
                ah[mi][1] = Bhi[r1 + k0 + tq];
                ah[mi][2] = Bhi[r0 + k0 + tq + 4];
                ah[mi][3] = Bhi[r1 + k0 + tq + 4];
                al[mi][0] = Blo[r0 + k0 + tq];
                al[mi][1] = Blo[r1 + k0 + tq];
                al[mi][2] = Blo[r0 + k0 + tq + 4];
                al[mi][3] = Blo[r1 + k0 + tq + 4];
            }
            #pragma unroll
            for (int ni = 0; ni < 3; ni++) {
                int c0 = (warp * 24 + ni * 8 + gq) * GBP2;
                bh[ni][0] = Bhi[c0 + k0 + tq];
                bh[ni][1] = Bhi[c0 + k0 + tq + 4];
                bl[ni][0] = Blo[c0 + k0 + tq];
                bl[ni][1] = Blo[c0 + k0 + tq + 4];
            }
            #pragma unroll
            for (int mi = 0; mi < 4; mi++)
                #pragma unroll
                for (int ni = 0; ni < 3; ni++) {
                    mma8(acc[mi][ni], ah[mi], bh[ni]);
                    mma8(acc[mi][ni], ah[mi], bl[ni]);
                    mma8(acc[mi][ni], al[mi], bh[ni]);
                }
        }
        __syncthreads();
    }

    // d2 + top-k in two 32-row passes (Bbuf reused as d2 [32][192])
    float* d2s = (float*)Bbuf;
    for (int pass = 0; pass < 2; pass++) {
        #pragma unroll
        for (int mi2 = 0; mi2 < 2; mi2++) {
            int mi = pass * 2 + mi2;
            #pragma unroll
            for (int ni = 0; ni < 3; ni++)
                #pragma unroll
                for (int e = 0; e < 4; e++) {
                    int lr = mi2 * 16 + gq + (e >> 1) * 8;
                    int c = warp * 24 + ni * 8 + 2 * tq + (e & 1);
                    float v2 = sq[i0 + pass * 32 + lr] + sq[c] - 2.f * acc[mi][ni][e];
                    d2s[lr * 192 + c] = fmaxf(v2, 0.f);
                }
        }
        __syncthreads();

        int tx = lane;
        for (int q = 0; q < 4; q++) {
            int r = warp * 4 + q;
            float val[6];
            #pragma unroll
            for (int s = 0; s < 6; s++) val[s] = d2s[r * 192 + tx + 32 * s];
            unsigned mask[6] = {0, 0, 0, 0, 0, 0};
            for (int pick = 0; pick < KTOP; pick++) {
                float bv = val[0]; int bi = tx;
                #pragma unroll
                for (int s = 1; s < 6; s++) {
                    float vv = val[s];
                    if (vv < bv) { bv = vv; bi = tx + 32 * s; }
                }
                #pragma unroll
                for (int o = 16; o; o >>= 1) {
                    float ov = __shfl_down_sync(0xffffffffu, bv, o);
                    int   oi = __shfl_down_sync(0xffffffffu, bi, o);
                    if (ov < bv || (ov == bv && oi < bi)) { bv = ov; bi = oi; }
                }
                bi = __shfl_sync(0xffffffffu, bi, 0);
                if ((bi & 31) == tx) val[bi >> 5] = FLT_MAX;
                mask[bi >> 5] |= 1u << (bi & 31);
            }
            if (tx == 0) {
                int e = i0 + pass * 32 + r;
                int u = e / 3;
                mask[u >> 5]           |= 1u << (u & 31);
                mask[(u + 64) >> 5]    |= 1u << ((u + 64) & 31);
                mask[(u + 128) >> 5]   |= 1u << ((u + 128) & 31);
                #pragma unroll
                for (int w = 0; w < 6; w++)
                    g_H[(size_t)(d * M + e) * 6 + w] = mask[w];
            }
        }
        __syncthreads();
    }
}

// ---------------- K3: X = feat @ W_fc + b_fc  (tf32 mma, 128x128 tile) ----------------
#define FAP 36
#define FBP 136
__global__ void __launch_bounds__(256) k_fc_mma(const float* Wfc, const float* bfc) {
    __shared__ unsigned sA[128 * FAP];
    __shared__ unsigned sB[32 * FBP];
    int bn = blockIdx.x, bm = blockIdx.y;
    int tid = threadIdx.x, lane = tid & 31, warp = tid >> 5;
    int wy = warp >> 1, wx = warp & 1;
    int gq = lane >> 2, tq = lane & 3;

    float acc[2][8][4];
    #pragma unroll
    for (int mi = 0; mi < 2; mi++)
        #pragma unroll
        for (int ni = 0; ni < 8; ni++)
            #pragma unroll
            for (int e = 0; e < 4; e++) acc[mi][ni][e] = 0.f;

    for (int kc = 0; kc < DIMF; kc += 32) {
        #pragma unroll
        for (int it = 0; it < 4; it++) {
            int idx = tid + it * 256;
            int r = idx >> 3, c = (idx & 7) * 4;
            cp16(sA + r * FAP + c, g_fh + (size_t)(bm * 128 + r) * DIMF + kc + c);
        }
        cp_commit();
        #pragma unroll
        for (int it = 0; it < 4; it++) {
            int idx = tid + it * 256;
            int kr = idx >> 5, n4 = (idx & 31) * 4;
            float4 wv = *(const float4*)(Wfc + (size_t)(kc + kr) * G + bn * 128 + n4);
            sB[kr * FBP + n4]     = f2tf(wv.x);
            sB[kr * FBP + n4 + 1] = f2tf(wv.y);
            sB[kr * FBP + n4 + 2] = f2tf(wv.z);
            sB[kr * FBP + n4 + 3] = f2tf(wv.w);
        }
        asm volatile("cp.async.wait_group 0;");
        __syncthreads();
        #pragma unroll
        for (int k0 = 0; k0 < 32; k0 += 8) {
            unsigned af[2][4], bf[8][2];
            #pragma unroll
            for (int mi = 0; mi < 2; mi++) {
                int row = wy * 32 + mi * 16;
                af[mi][0] = sA[(row + gq) * FAP + k0 + tq];
                af[mi][1] = sA[(row + gq + 8) * FAP + k0 + tq];
                af[mi][2] = sA[(row + gq) * FAP + k0 + tq + 4];
                af[mi][3] = sA[(row + gq + 8) * FAP + k0 + tq + 4];
            }
            #pragma unroll
            for (int ni = 0; ni < 8; ni++) {
                int c0 = wx * 64 + ni * 8;
                bf[ni][0] = sB[(k0 + tq) * FBP + c0 + gq];
                bf[ni][1] = sB[(k0 + tq + 4) * FBP + c0 + gq];
            }
            #pragma unroll
            for (int mi = 0; mi < 2; mi++)
                #pragma unroll
                for (int ni = 0; ni < 8; ni++)
                    mma8(acc[mi][ni], af[mi], bf[ni]);
        }
        __syncthreads();
    }
    #pragma unroll
    for (int mi = 0; mi < 2; mi++)
        #pragma unroll
        for (int ni = 0; ni < 8; ni++)
            #pragma unroll
            for (int e = 0; e < 4; e++) {
                int r  = bm * 128 + wy * 32 + mi * 16 + gq + (e >> 1) * 8;
                int cc = bn * 128 + wx * 64 + ni * 8 + 2 * tq + (e & 1);
                g_X[(size_t)r * G + cc] = acc[mi][ni][e] + bfc[cc];
            }
}

// ---------------- K4: fused hypergraph hops, 64-col blocks ----------------
#define BP4 72     // B pitch (64 + 8)
#define SEP2 66    // E tile pitch (64 + 2)
#define FONE 0x3F800000u
#define AGG_SMEM ((192*6 + 192*6 + 2*16*BP4)*4 + (192 + 192 + 192*SEP2)*4)
__global__ void __launch_bounds__(256) k_agg_f() {
    extern __shared__ __align__(16) char asm_[];
    unsigned* sHw  = (unsigned*)asm_;                 // [edge][node-word]
    unsigned* sHT  = sHw + 192 * 6;                   // [node][edge-word]
    unsigned* sB   = sHT + 192 * 6;                   // hi | lo
    float*    sdegE = (float*)(sB + 2 * 16 * BP4);
    float*    sdegV = sdegE + 192;
    float*    sE   = sdegV + 192;                     // 192 x SEP2
    int d = blockIdx.y, n0 = blockIdx.x * 64;
    int tid = threadIdx.x, lane = tid & 31, warp = tid >> 5;
    int wy = warp >> 1, wx = warp & 1;        // wy: 48 rows, wx: 32 cols
    int gq = lane >> 2, tq = lane & 3;

    for (int i = tid; i < 192 * 6; i += 256) sHw[i] = g_H[(size_t)(d * M) * 6 + i];
    __syncthreads();

    // 32x32 bit-transpose blocks: 6x6 blocks over 8 warps
    for (int blk = warp; blk < 36; blk += 8) {
        int eb = blk / 6, nb = blk % 6;
        unsigned x = sHw[(eb * 32 + lane) * 6 + nb];
        #pragma unroll
        for (int i = 16; i >= 1; i >>= 1) {
            unsigned m = 0xFFFFFFFFu / ((1u << i) + 1u);
            unsigned y = __shfl_xor_sync(0xffffffffu, x, i);
            x = (lane & i) ? (((y >> i) & m) | (x & ~m))
                           : ((x & m) | ((y & m) << i));
        }
        sHT[(nb * 32 + lane) * 6 + eb] = x;
    }
    __syncthreads();

    if (tid < 192) {
        int dege = 0, degv = 0;
        #pragma unroll
        for (int w = 0; w < 6; w++) {
            dege += __popc(sHw[tid * 6 + w]);
            degv += __popc(sHT[tid * 6 + w]);
        }
        sdegE[tid] = 1.f / (float)dege;
        sdegV[tid] = 1.f / (float)degv;
    }

    float acc[3][4][4];
    #pragma unroll
    for (int mi = 0; mi < 3; mi++)
        #pragma unroll
        for (int ni = 0; ni < 4; ni++)
            #pragma unroll
            for (int e = 0; e < 4; e++) acc[mi][ni][e] = 0.f;

    int kr = tid >> 4, c4 = (tid & 15) * 4;   // 16 rows x 64 cols, float4/thread
    float4 nxt = *(const float4*)(g_X + (size_t)(d * M + kr) * G + n0 + c4);

    // ---- hop 0: E = (H @ X) / deg_e ----
    for (int kc = 0; kc < 192; kc += 16) {
        hilo(nxt.x, sB[kr * BP4 + c4],     sB[16 * BP4 + kr * BP4 + c4]);
        hilo(nxt.y, sB[kr * BP4 + c4 + 1], sB[16 * BP4 + kr * BP4 + c4 + 1]);
        hilo(nxt.z, sB[kr * BP4 + c4 + 2], sB[16 * BP4 + kr * BP4 + c4 + 2]);
        hilo(nxt.w, sB[kr * BP4 + c4 + 3], sB[16 * BP4 + kr * BP4 + c4 + 3]);
        __syncthreads();
        if (kc + 16 < 192)
            nxt = *(const float4*)(g_X + (size_t)(d * M + kc + 16 + kr) * G + n0 + c4);
        int kw = kc >> 5, sh = kc & 31;
        unsigned hw0[3], hw1[3];
        #pragma unroll
        for (int mi = 0; mi < 3; mi++) {
            int e0 = wy * 48 + mi * 16 + gq;
            hw0[mi] = sHw[e0 * 6 + kw];
            hw1[mi] = sHw[(e0 + 8) * 6 + kw];
        }
        #pragma unroll
        for (int k0 = 0; k0 < 16; k0 += 8) {
            unsigned af[3][4], bh[4][2], bl[4][2];
            int b0 = sh + k0 + tq;
            #pragma unroll
            for (int mi = 0; mi < 3; mi++) {
                af[mi][0] = ((hw0[mi] >> b0) & 1u)       ? FONE : 0u;
                af[mi][1] = ((hw1[mi] >> b0) & 1u)       ? FONE : 0u;
                af[mi][2] = ((hw0[mi] >> (b0 + 4)) & 1u) ? FONE : 0u;
                af[mi][3] = ((hw1[mi] >> (b0 + 4)) & 1u) ? FONE : 0u;
            }
            #pragma unroll
            for (int ni = 0; ni < 4; ni++) {
                int c0 = wx * 32 + ni * 8;
                bh[ni][0] = sB[(k0 + tq) * BP4 + c0 + gq];
                bh[ni][1] = sB[(k0 + tq + 4) * BP4 + c0 + gq];
                bl[ni][0] = sB[16 * BP4 + (k0 + tq) * BP4 + c0 + gq];
                bl[ni][1] = sB[16 * BP4 + (k0 + tq + 4) * BP4 + c0 + gq];
            }
            #pragma unroll
            for (int mi = 0; mi < 3; mi++)
                #pragma unroll
                for (int ni = 0; ni < 4; ni++) {
                    mma8(acc[mi][ni], af[mi], bh[ni]);
                    mma8(acc[mi][ni], af[mi], bl[ni]);
                }
        }
        __syncthreads();
    }
    #pragma unroll
    for (int mi = 0; mi < 3; mi++)
        #pragma unroll
        for (int ni = 0; ni < 4; ni++)
            #pragma unroll
            for (int e = 0; e < 4; e++) {
                int r = wy * 48 + mi * 16 + gq + (e >> 1) * 8;
                int c = wx * 32 + ni * 8 + 2 * tq + (e & 1);
                sE[r * SEP2 + c] = acc[mi][ni][e] * sdegE[r];
            }
    #pragma unroll
    for (int mi = 0; mi < 3; mi++)
        #pragma unroll
        for (int ni = 0; ni < 4; ni++)
            #pragma unroll
            for (int e = 0; e < 4; e++) acc[mi][ni][e] = 0.f;
    __syncthreads();

    // ---- hop 1: Y = (H^T @ E) / deg_v  (A bits from node-major sHT) ----
    for (int kc = 0; kc < 192; kc += 16) {
        float e0v = sE[(kc + kr) * SEP2 + c4];
        float e1v = sE[(kc + kr) * SEP2 + c4 + 1];
        float e2v = sE[(kc + kr) * SEP2 + c4 + 2];
        float e3v = sE[(kc + kr) * SEP2 + c4 + 3];
        hilo(e0v, sB[kr * BP4 + c4],     sB[16 * BP4 + kr * BP4 + c4]);
        hilo(e1v, sB[kr * BP4 + c4 + 1], sB[16 * BP4 + kr * BP4 + c4 + 1]);
        hilo(e2v, sB[kr * BP4 + c4 + 2], sB[16 * BP4 + kr * BP4 + c4 + 2]);
        hilo(e3v, sB[kr * BP4 + c4 + 3], sB[16 * BP4 + kr * BP4 + c4 + 3]);
        __syncthreads();
        int kw = kc >> 5, sh = kc & 31;
        unsigned ht0[3], ht1[3];
        #pragma unroll
        for (int mi = 0; mi < 3; mi++) {
            int nrow = wy * 48 + mi * 16 + gq;
            ht0[mi] = sHT[nrow * 6 + kw];
            ht1[mi] = sHT[(nrow + 8) * 6 + kw];
        }
        #pragma unroll
        for (int k0 = 0; k0 < 16; k0 += 8) {
            unsigned af[3][4], bh[4][2], bl[4][2];
            int b0 = sh + k0 + tq;
            #pragma unroll
            for (int mi = 0; mi < 3; mi++) {
                af[mi][0] = ((ht0[mi] >> b0) & 1u)       ? FONE : 0u;
                af[mi][1] = ((ht1[mi] >> b0) & 1u)       ? FONE : 0u;
                af[mi][2] = ((ht0[mi] >> (b0 + 4)) & 1u) ? FONE : 0u;
                af[mi][3] = ((ht1[mi] >> (b0 + 4)) & 1u) ? FONE : 0u;
            }
            #pragma unroll
            for (int ni = 0; ni < 4; ni++) {
                int c0 = wx * 32 + ni * 8;
                bh[ni][0] = sB[(k0 + tq) * BP4 + c0 + gq];
                bh[ni][1] = sB[(k0 + tq + 4) * BP4 + c0 + gq];
                bl[ni][0] = sB[16 * BP4 + (k0 + tq) * BP4 + c0 + gq];
                bl[ni][1] = sB[16 * BP4 + (k0 + tq + 4) * BP4 + c0 + gq];
            }
            #pragma unroll
            for (int mi = 0; mi < 3; mi++)
                #pragma unroll
                for (int ni = 0; ni < 4; ni++) {
                    mma8(acc[mi][ni], af[mi], bh[ni]);
                    mma8(acc[mi][ni], af[mi], bl[ni]);
                }
        }
        __syncthreads();
    }
    #pragma unroll
    for (int mi = 0; mi < 3; mi++)
        #pragma unroll
        for (int ni = 0; ni < 4; ni++)
            #pragma unroll
            for (int e = 0; e < 4; e++) {
                int r = wy * 48 + mi * 16 + gq + (e >> 1) * 8;
                int c = n0 + wx * 32 + ni * 8 + 2 * tq + (e & 1);
                g_Y[(size_t)(d * M + r) * G + c] = acc[mi][ni][e] * sdegV[r];
            }
}

// ---------------- K6: out = relu(Y @ W_h + b_h) (tf32 mma), regrouped ----------------
__global__ void __launch_bounds__(256) k_out_mma(const float* Wh, const float* bh,
                                                 float* out) {
    __shared__ unsigned sA[128 * FAP];
    __shared__ unsigned sB[32 * FBP];
    int bn = blockIdx.x, bm = blockIdx.y;
    int tid = threadIdx.x, lane = tid & 31, warp = tid >> 5;
    int wy = warp >> 1, wx = warp & 1;
    int gq = lane >> 2, tq = lane & 3;

    float acc[2][8][4];
    #pragma unroll
    for (int mi = 0; mi < 2; mi++)
        #pragma unroll
        for (int ni = 0; ni < 8; ni++)
            #pragma unroll
            for (int e = 0; e < 4; e++) acc[mi][ni][e] = 0.f;

    for (int kc = 0; kc < G; kc += 32) {
        #pragma unroll
        for (int it = 0; it < 4; it++) {
            int idx = tid + it * 256;
            int r = idx >> 3, c = (idx & 7) * 4;
            float4 xv = *(const float4*)(g_Y + (size_t)(bm * 128 + r) * G + kc + c);
            sA[r * FAP + c]     = f2tf(xv.x);
            sA[r * FAP + c + 1] = f2tf(xv.y);
            sA[r * FAP + c + 2] = f2tf(xv.z);
            sA[r * FAP + c + 3] = f2tf(xv.w);
        }
        #pragma unroll
        for (int it = 0; it < 4; it++) {
            int idx = tid + it * 256;
            int kr = idx >> 5, n4 = (idx & 31) * 4;
            float4 wv = *(const float4*)(Wh + (size_t)(kc + kr) * G + bn * 128 + n4);
            sB[kr * FBP + n4]     = f2tf(wv.x);
            sB[kr * FBP + n4 + 1] = f2tf(wv.y);
            sB[kr * FBP + n4 + 2] = f2tf(wv.z);
            sB[kr * FBP + n4 + 3] = f2tf(wv.w);
        }
        __syncthreads();
        #pragma unroll
        for (int k0 = 0; k0 < 32; k0 += 8) {
            unsigned af[2][4], bf[8][2];
            #pragma unroll
            for (int mi = 0; mi < 2; mi++) {
                int row = wy * 32 + mi * 16;
                af[mi][0] = sA[(row + gq) * FAP + k0 + tq];
                af[mi][1] = sA[(row + gq + 8) * FAP + k0 + tq];
                af[mi][2] = sA[(row + gq) * FAP + k0 + tq + 4];
                af[mi][3] = sA[(row + gq + 8) * FAP + k0 + tq + 4];
            }
            #pragma unroll
            for (int ni = 0; ni < 8; ni++) {
                int c0 = wx * 64 + ni * 8;
                bf[ni][0] = sB[(k0 + tq) * FBP + c0 + gq];
                bf[ni][1] = sB[(k0 + tq + 4) * FBP + c0 + gq];
            }
            #pragma unroll
            for (int mi = 0; mi < 2; mi++)
                #pragma unroll
                for (int ni = 0; ni < 8; ni++)
                    mma8(acc[mi][ni], af[mi], bf[ni]);
        }
        __syncthreads();
    }
    #pragma unroll
    for (int mi = 0; mi < 2; mi++)
        #pragma unroll
        for (int ni = 0; ni < 8; ni++)
            #pragma unroll
            for (int e = 0; e < 4; e++) {
                int gn = bm * 128 + wy * 32 + mi * 16 + gq + (e >> 1) * 8;
                int gc = bn * 128 + wx * 64 + ni * 8 + 2 * tq + (e & 1);
                int dd = gn / M, n = gn % M, mod = n >> 6, ii = n & 63;
                out[(size_t)(dd * L + ii) * 768 + mod * 256 + gc] =
                    fmaxf(acc[mi][ni][e] + bh[gc], 0.f);
            }
}

// ---------------- K7: norms, diag sims, zero LSE accumulators, bf16 convert ----------------
__global__ void k_norm(const float* out) {
    int i = blockIdx.x;
    int tid = threadIdx.x;
    float tv = out[(size_t)i * 768 + tid];
    float av = out[(size_t)i * 768 + 256 + tid];
    float vv = out[(size_t)i * 768 + 512 + tid];
    float q[6] = { tv * tv, av * av, vv * vv, tv * av, tv * vv, av * vv };
    __shared__ float red[6][8];
    __shared__ float sinv[3];
    int lane = tid & 31, w = tid >> 5;
    #pragma unroll
    for (int o = 16; o; o >>= 1)
        #pragma unroll
        for (int k = 0; k < 6; k++) q[k] += __shfl_down_sync(0xffffffffu, q[k], o);
    if (lane == 0)
        #pragma unroll
        for (int k = 0; k < 6; k++) red[k][w] = q[k];
    __syncthreads();
    if (tid == 0) {
        float s[6];
        #pragma unroll
        for (int k = 0; k < 6; k++) {
            s[k] = 0.f;
            #pragma unroll
            for (int w2 = 0; w2 < 8; w2++) s[k] += red[k][w2];
        }
        float it = 1.f / (sqrtf(s[0]) + 1e-8f);
        float ia = 1.f / (sqrtf(s[1]) + 1e-8f);
        float iv = 1.f / (sqrtf(s[2]) + 1e-8f);
        sinv[0] = it * SQTAUI; sinv[1] = ia * SQTAUI; sinv[2] = iv * SQTAUI;
        g_diag[i]             = s[3] * it * ia * TAUINV;
        g_diag[NROWS + i]     = s[4] * it * iv * TAUINV;
        g_diag[2 * NROWS + i] = s[5] * ia * iv * TAUINV;
        g_rowsum[i] = 0.f; g_rowsum[NROWS + i] = 0.f; g_rowsum[2 * NROWS + i] = 0.f;
        g_colsum[i] = 0.f; g_colsum[NROWS + i] = 0.f; g_colsum[2 * NROWS + i] = 0.f;
    }
    __syncthreads();
    g_nb[((size_t)0 * NROWS + i) * G + tid] = __float2bfloat16(tv * sinv[0]);
    g_nb[((size_t)1 * NROWS + i) * G + tid] = __float2bfloat16(av * sinv[1]);
    g_nb[((size_t)2 * NROWS + i) * G + tid] = __float2bfloat16(vv * sinv[2]);
}

// ---------------- K8: bf16 sim tiles; X panel resident, 4 col tiles per block ----------------
#define SPITCH 40
#define XPITCH 264
#define SIM_SMEM (128*XPITCH*2 + 2*128*SPITCH*2 + 256*4)
__global__ void __launch_bounds__(256) k_sim_mma() {
    extern __shared__ __align__(16) char dsm[];
    __nv_bfloat16* sXp = (__nv_bfloat16*)dsm;                       // 128 x 256 panel
    __nv_bfloat16* sY  = sXp + 128 * XPITCH;                         // 2 x 128 x SPITCH
    float* srow = (float*)(sY + 2 * 128 * SPITCH);
    float* scol = srow + 128;

    int p = blockIdx.z;
    int mx = (p == 2) ? 1 : 0;
    int my = (p == 0) ? 1 : 2;
    int row0 = blockIdx.y * 128;
    int tid = threadIdx.x, lane = tid & 31, warp = tid >> 5;
    int wy = warp >> 1, wx = warp & 1;      // warp tile: 32 rows x 64 cols

    const __nv_bfloat16* xg = g_nb + ((size_t)mx * NROWS + row0) * G;

    #pragma unroll
    for (int it = 0; it < 16; it++) {
        int idx = tid + it * 256;
        int r = idx >> 5, c = (idx & 31) * 8;
        cp16(sXp + r * XPITCH + c, xg + (size_t)r * G + c);
    }
    cp_commit();
    asm volatile("cp.async.wait_group 0;");
    __syncthreads();

    int lr = tid >> 2, lc = (tid & 3) * 8;
    int lr2 = lr + 64;

    for (int j = 0; j < 4; j++) {
        int col0 = (blockIdx.x * 4 + j) * 128;
        const __nv_bfloat16* yg = g_nb + ((size_t)my * NROWS + col0) * G;

        float acc[2][8][4];
        #pragma unroll
        for (int mi = 0; mi < 2; mi++)
            #pragma unroll
            for (int ni = 0; ni < 8; ni++)
                #pragma unroll
                for (int r = 0; r < 4; r++) acc[mi][ni][r] = 0.f;

        cp16(sY + lr * SPITCH + lc,  yg + (size_t)lr * G + lc);
        cp16(sY + lr2 * SPITCH + lc, yg + (size_t)lr2 * G + lc);
        cp_commit();

        #pragma unroll
        for (int c = 0; c < 8; c++) {
            int cur = c & 1;
            if (c < 7) {
                int nb = (c + 1) & 1, kc2 = (c + 1) * 32;
                cp16(sY + nb * 128 * SPITCH + lr * SPITCH + lc,
                     yg + (size_t)lr * G + kc2 + lc);
                cp16(sY + nb * 128 * SPITCH + lr2 * SPITCH + lc,
                     yg + (size_t)lr2 * G + kc2 + lc);
                cp_commit();
                asm volatile("cp.async.wait_group 1;");
            } else {
                asm volatile("cp.async.wait_group 0;");
            }
            __syncthreads();
            int kc = c * 32;
            #pragma unroll
            for (int ks = 0; ks < 2; ks++) {
                int k0 = ks * 16;
                unsigned A[2][4];
                #pragma unroll
                for (int mi = 0; mi < 2; mi++) {
                    int r = wy * 32 + mi * 16 + ((lane >> 3) & 1) * 8 + (lane & 7);
                    int cc = kc + k0 + (lane >> 4) * 8;
                    unsigned ad = (unsigned)__cvta_generic_to_shared(sXp + r * XPITCH + cc);
                    asm volatile("ldmatrix.sync.aligned.m8n8.x4.shared.b16 {%0,%1,%2,%3},[%4];"
                        : "=r"(A[mi][0]), "=r"(A[mi][1]), "=r"(A[mi][2]), "=r"(A[mi][3])
                        : "r"(ad));
                }
                unsigned B[8][2];
                #pragma unroll
                for (int nb2 = 0; nb2 < 4; nb2++) {
                    int r = wx * 64 + nb2 * 16 + (lane >> 4) * 8 + (lane & 7);
                    int cc = k0 + ((lane >> 3) & 1) * 8;
                    unsigned ad = (unsigned)__cvta_generic_to_shared(
                        sY + cur * 128 * SPITCH + r * SPITCH + cc);
                    asm volatile("ldmatrix.sync.aligned.m8n8.x4.shared.b16 {%0,%1,%2,%3},[%4];"
                        : "=r"(B[2 * nb2][0]), "=r"(B[2 * nb2][1]),
                          "=r"(B[2 * nb2 + 1][0]), "=r"(B[2 * nb2 + 1][1])
                        : "r"(ad));
                }
                #pragma unroll
                for (int mi = 0; mi < 2; mi++)
                    #pragma unroll
                    for (int ni = 0; ni < 8; ni++)
                        asm volatile(
                            "mma.sync.aligned.m16n8k16.row.col.f32.bf16.bf16.f32 "
                            "{%0,%1,%2,%3},{%4,%5,%6,%7},{%8,%9},{%0,%1,%2,%3};"
                            : "+f"(acc[mi][ni][0]), "+f"(acc[mi][ni][1]),
                              "+f"(acc[mi][ni][2]), "+f"(acc[mi][ni][3])
                            : "r"(A[mi][0]), "r"(A[mi][1]), "r"(A[mi][2]), "r"(A[mi][3]),
                              "r"(B[ni][0]), "r"(B[ni][1]));
            }
            __syncthreads();
        }

        if (tid < 128) { srow[tid] = 0.f; scol[tid] = 0.f; }
        __syncthreads();

        float rowp[2][2] = {{0.f, 0.f}, {0.f, 0.f}};
        float colp[8][2];
        #pragma unroll
        for (int ni = 0; ni < 8; ni++) { colp[ni][0] = 0.f; colp[ni][1] = 0.f; }
        #pragma unroll
        for (int mi = 0; mi < 2; mi++)
            #pragma unroll
            for (int ni = 0; ni < 8; ni++)
                #pragma unroll
                for (int r = 0; r < 4; r++) {
                    float e = __expf(acc[mi][ni][r]);
                    rowp[mi][r >> 1] += e;
                    colp[ni][r & 1] += e;
                }

        #pragma unroll
        for (int mi = 0; mi < 2; mi++)
            #pragma unroll
            for (int h = 0; h < 2; h++) {
                float vv = rowp[mi][h];
                vv += __shfl_xor_sync(0xffffffffu, vv, 1);
                vv += __shfl_xor_sync(0xffffffffu, vv, 2);
                if ((lane & 3) == 0)
                    atomicAdd(&srow[wy * 32 + mi * 16 + (lane >> 2) + h * 8], vv);
            }
        #pragma unroll
        for (int ni = 0; ni < 8; ni++)
            #pragma unroll
            for (int s2 = 0; s2 < 2; s2++) {
                float vv = colp[ni][s2];
                vv += __shfl_xor_sync(0xffffffffu, vv, 4);
                vv += __shfl_xor_sync(0xffffffffu, vv, 8);
                vv += __shfl_xor_sync(0xffffffffu, vv, 16);
                if (lane < 4)
                    atomicAdd(&scol[wx * 64 + ni * 8 + lane * 2 + s2], vv);
            }
        __syncthreads();
        if (tid < 128) {
            atomicAdd(&g_rowsum[p * NROWS + row0 + tid], srow[tid]);
            atomicAdd(&g_colsum[p * NROWS + col0 + tid], scol[tid]);
        }
        __syncthreads();
    }
}

// ---------------- K9: final loss reduction ----------------
__global__ void k_loss(float* out, int out_size) {
    int tid = threadIdx.x;
    float s = 0.f;
    for (int idx = tid; idx < 3 * NROWS; idx += 256) {
        float dg = g_diag[idx];
        s += 2.f * dg - logf(g_rowsum[idx]) - logf(g_colsum[idx]);
    }
    __shared__ float red[8];
    int lane = tid & 31, w = tid >> 5;
    #pragma unroll
    for (int o = 16; o; o >>= 1) s += __shfl_down_sync(0xffffffffu, s, o);
    if (lane == 0) red[w] = s;
    __syncthreads();
    if (tid == 0) {
        float tot = 0.f;
        #pragma unroll
        for (int w2 = 0; w2 < 8; w2++) tot += red[w2];
        float loss = -tot / (2.f * 3.f * (float)NROWS);
        if (out_size > NROWS * 768) out[NROWS * 768] = loss;
    }
}

// ---------------- launcher ----------------
extern "C" void kernel_launch(void* const* d_in, const int* in_sizes, int n_in,
                              void* d_out, int out_size) {
    const float* t   = (const float*)d_in[0];
    const float* a   = (const float*)d_in[1];
    const float* v   = (const float*)d_in[2];
    const float* Wfc = (const float*)d_in[3];
    const float* bfc = (const float*)d_in[4];
    const float* Wh  = (const float*)d_in[5];
    const float* bh  = (const float*)d_in[6];
    float* out = (float*)d_out;

    cudaFuncSetAttribute(k_sim_mma,
        cudaFuncAttributeMaxDynamicSharedMemorySize, SIM_SMEM);
    cudaFuncSetAttribute(k_agg_f,
        cudaFuncAttributeMaxDynamicSharedMemorySize, AGG_SMEM);

    k_sq<<<NNODE / 8, 256>>>(t, a, v);
    k_gram_mma<<<dim3(3, 64), 256>>>();
    k_fc_mma<<<dim3(2, 96), 256>>>(Wfc, bfc);
    k_agg_f<<<dim3(4, 64), 256, AGG_SMEM>>>();
    k_out_mma<<<dim3(2, 96), 256>>>(Wh, bh, out);
    k_norm<<<NROWS, 256>>>(out);
    k_sim_mma<<<dim3(8, 32, 3), 256, SIM_SMEM>>>();
    k_loss<<<1, 256>>>(out, out_size);
}

// round 12
// speedup vs baseline: 1.1465x; 1.1465x over previous
#include <cuda_runtime.h>
#include <cuda_bf16.h>
#include <math.h>
#include <float.h>

#define D 64
#define L 64
#define DIMF 512
#define G 256
#define M 192                 // 3*L nodes (= hyperedges) per dialogue
#define KTOP 12
#define NROWS 4096            // D*L
#define NNODE (D*M)           // 12288
#define TAUINV (1.0f/0.07f)
#define SQTAUI 3.7796447300922722f   // sqrt(1/0.07)

// ---- scratch (static device arrays; no allocation allowed) ----
__device__ float    g_sq[NNODE];
__device__ unsigned g_fh[(size_t)NNODE*DIMF];   // tf32 hi of features
__device__ unsigned g_fl[(size_t)NNODE*DIMF];   // tf32 lo of features
__device__ unsigned g_H[NNODE*6];       // 192-bit incidence mask per edge
__device__ float    g_X[NNODE*G];
__device__ float    g_Y[NNODE*G];
__device__ float    g_diag[3*NROWS];
__device__ float    g_rowsum[3*NROWS];
__device__ float    g_colsum[3*NROWS];
__device__ __nv_bfloat16 g_nb[(size_t)3*NROWS*G];   // normalized bf16 features (loss path only)

__device__ __forceinline__ const float* feat_row(int d, int n,
        const float* t, const float* a, const float* v) {
    int mod = n >> 6, i = n & 63;
    const float* base = (mod == 0) ? t : (mod == 1) ? a : v;
    return base + (size_t)(d * L + i) * DIMF;
}

// ---- tf32 helpers ----
__device__ __forceinline__ unsigned f2tf(float x) {
    unsigned u; asm("cvt.rna.tf32.f32 %0, %1;" : "=r"(u) : "f"(x)); return u;
}
__device__ __forceinline__ void hilo(float x, unsigned& h, unsigned& l) {
    h = f2tf(x);
    l = f2tf(x - __uint_as_float(h));
}
__device__ __forceinline__ void mma8(float* c, const unsigned* a, const unsigned* b) {
    asm volatile("mma.sync.aligned.m16n8k8.row.col.f32.tf32.tf32.f32 "
        "{%0,%1,%2,%3},{%4,%5,%6,%7},{%8,%9},{%0,%1,%2,%3};"
        : "+f"(c[0]), "+f"(c[1]), "+f"(c[2]), "+f"(c[3])
        : "r"(a[0]), "r"(a[1]), "r"(a[2]), "r"(a[3]), "r"(b[0]), "r"(b[1]));
}

// ---- cp.async helpers ----
__device__ __forceinline__ void cp16(void* dst_smem, const void* src) {
    unsigned ad = (unsigned)__cvta_generic_to_shared(dst_smem);
    asm volatile("cp.async.cg.shared.global [%0],[%1],16;" :: "r"(ad), "l"(src));
}
__device__ __forceinline__ void cp_commit() {
    asm volatile("cp.async.commit_group;");
}

// ---------------- K1: per-node squared norms + hi/lo precompute ----------------
__global__ void k_sq(const float* t, const float* a, const float* v) {
    int warp = (blockIdx.x * blockDim.x + threadIdx.x) >> 5;
    int lane = threadIdx.x & 31;
    if (warp >= NNODE) return;
    int d = warp / M, n = warp % M;
    const float* r = feat_row(d, n, t, a, v);
    float s = 0.f;
    #pragma unroll
    for (int c = lane; c < DIMF; c += 32) { float x = r[c]; s += x * x; }
    unsigned* fh = g_fh + (size_t)warp * DIMF;
    unsigned* fl = g_fl + (size_t)warp * DIMF;
    #pragma unroll
    for (int c0 = lane * 4; c0 < DIMF; c0 += 128) {
        float4 x = *(const float4*)(r + c0);
        uint4 h, l;
        hilo(x.x, h.x, l.x); hilo(x.y, h.y, l.y);
        hilo(x.z, h.z, l.z); hilo(x.w, h.w, l.w);
        *(uint4*)(fh + c0) = h;
        *(uint4*)(fl + c0) = l;
    }
    #pragma unroll
    for (int o = 16; o; o >>= 1) s += __shfl_down_sync(0xffffffffu, s, o);
    if (lane == 0) g_sq[warp] = s;
}

// ---------------- K2: 3xTF32 gram + d2 + top-12 + incidence masks (R10 version) ----------------
#define GBP2 20
__global__ void __launch_bounds__(256) k_gram_mma() {
    __shared__ unsigned Bbuf[2 * 192 * GBP2];        // hi | lo ; reused as d2 [32][192]
    __shared__ float sq[M];
    unsigned* Bhi = Bbuf;
    unsigned* Blo = Bbuf + 192 * GBP2;

    int d = blockIdx.y, i0 = blockIdx.x * 32;
    int tid = threadIdx.x, lane = tid & 31, warp = tid >> 5;
    int gq = lane >> 2, tq = lane & 3;
    if (tid < M) sq[tid] = g_sq[d * M + tid];
    size_t base = (size_t)(d * M) * DIMF;

    float acc[2][3][4];
    #pragma unroll
    for (int mi = 0; mi < 2; mi++)
        #pragma unroll
        for (int ni = 0; ni < 3; ni++)
            #pragma unroll
            for (int e = 0; e < 4; e++) acc[mi][ni][e] = 0.f;

    for (int kc = 0; kc < DIMF; kc += 16) {
        #pragma unroll
        for (int it = 0; it < 3; it++) {
            int idx = tid + it * 256;              // 0..767
            int n = idx >> 2, k4 = (idx & 3) * 4;
            cp16(Bhi + n * GBP2 + k4, g_fh + base + (size_t)n * DIMF + kc + k4);
            cp16(Blo + n * GBP2 + k4, g_fl + base + (size_t)n * DIMF + kc + k4);
        }
        cp_commit();
        asm volatile("cp.async.wait_group 0;");
        __syncthreads();
        #pragma unroll
        for (int k0 = 0; k0 < 16; k0 += 8) {
            unsigned ah[2][4], al[2][4], bh[3][2], bl[3][2];
            #pragma unroll
            for (int mi = 0; mi < 2; mi++) {
                int r0 = (i0 + mi * 16 + gq) * GBP2;
                int r1 = r0 + 8 * GBP2;
                ah[mi][0] = Bhi[r0 + k0 + tq];
                ah[mi][1] = Bhi[r1 + k0 + tq];
                ah[mi][2] = Bhi[r0 + k0 + tq + 4];
                ah[mi][3] = Bhi[r1 + k0 + tq + 4];
                al[mi][0] = Blo[r0 + k0 + tq];
                al[mi][1] = Blo[r1 + k0 + tq];
                al[mi][2] = Blo[r0 + k0 + tq + 4];
                al[mi][3] = Blo[r1 + k0 + tq + 4];
            }
            #pragma unroll
            for (int ni = 0; ni < 3; ni++) {
                int c0 = (warp * 24 + ni * 8 + gq) * GBP2;
                bh[ni][0] = Bhi[c0 + k0 + tq];
                bh[ni][1] = Bhi[c0 + k0 + tq + 4];
                bl[ni][0] = Blo[c0 + k0 + tq];
                bl[ni][1] = Blo[c0 + k0 + tq + 4];
            }
            #pragma unroll
            for (int mi = 0; mi < 2; mi++)
                #pragma unroll
                for (int ni = 0; ni < 3; ni++) {
                    mma8(acc[mi][ni], ah[mi], bh[ni]);
                    mma8(acc[mi][ni], ah[mi], bl[ni]);
                    mma8(acc[mi][ni], al[mi], bh[ni]);
                }
        }
        __syncthreads();
    }

    float* d2s = (float*)Bbuf;
    #pragma unroll
    for (int mi = 0; mi < 2; mi++)
        #pragma unroll
        for (int ni = 0; ni < 3; ni++)
            #pragma unroll
            for (int e = 0; e < 4; e++) {
                int r = mi * 16 + gq + (e >> 1) * 8;
                int c = warp * 24 + ni * 8 + 2 * tq + (e & 1);
                float v2 = sq[i0 + r] + sq[c] - 2.f * acc[mi][ni][e];
                d2s[r * 192 + c] = fmaxf(v2, 0.f);
            }
    __syncthreads();

    int tx = lane;
    for (int q = 0; q < 4; q++) {
        int r = warp * 4 + q;
        float val[6];
        #pragma unroll
        for (int s = 0; s < 6; s++) val[s] = d2s[r * 192 + tx + 32 * s];
        unsigned mask[6] = {0, 0, 0, 0, 0, 0};
        for (int pick = 0; pick < KTOP; pick++) {
            float bv = val[0]; int bi = tx;
            #pragma unroll
            for (int s = 1; s < 6; s++) {
                float vv = val[s];
                if (vv < bv) { bv = vv; bi = tx + 32 * s; }
            }
            #pragma unroll
            for (int o = 16; o; o >>= 1) {
                float ov = __shfl_down_sync(0xffffffffu, bv, o);
                int   oi = __shfl_down_sync(0xffffffffu, bi, o);
                if (ov < bv || (ov == bv && oi < bi)) { bv = ov; bi = oi; }
            }
            bi = __shfl_sync(0xffffffffu, bi, 0);
            if ((bi & 31) == tx) val[bi >> 5] = FLT_MAX;
            mask[bi >> 5] |= 1u << (bi & 31);
        }
        if (tx == 0) {
            int e = i0 + r;
            int u = e / 3;
            mask[u >> 5]           |= 1u << (u & 31);
            mask[(u + 64) >> 5]    |= 1u << ((u + 64) & 31);
            mask[(u + 128) >> 5]   |= 1u << ((u + 128) & 31);
            #pragma unroll
            for (int w = 0; w < 6; w++)
                g_H[(size_t)(d * M + e) * 6 + w] = mask[w];
        }
    }
}

// ---------------- K3: X = feat @ W_fc + b_fc  (tf32 mma, 128x128 tile) ----------------
#define FAP 36
#define FBP 136
__global__ void __launch_bounds__(256) k_fc_mma(const float* Wfc, const float* bfc) {
    __shared__ unsigned sA[128 * FAP];
    __shared__ unsigned sB[32 * FBP];
    int bn = blockIdx.x, bm = blockIdx.y;
    int tid = threadIdx.x, lane = tid & 31, warp = tid >> 5;
    int wy = warp >> 1, wx = warp & 1;
    int gq = lane >> 2, tq = lane & 3;

    float acc[2][8][4];
    #pragma unroll
    for (int mi = 0; mi < 2; mi++)
        #pragma unroll
        for (int ni = 0; ni < 8; ni++)
            #pragma unroll
            for (int e = 0; e < 4; e++) acc[mi][ni][e] = 0.f;

    for (int kc = 0; kc < DIMF; kc += 32) {
        #pragma unroll
        for (int it = 0; it < 4; it++) {
            int idx = tid + it * 256;
            int r = idx >> 3, c = (idx & 7) * 4;
            cp16(sA + r * FAP + c, g_fh + (size_t)(bm * 128 + r) * DIMF + kc + c);
        }
        cp_commit();
        #pragma unroll
        for (int it = 0; it < 4; it++) {
            int idx = tid + it * 256;
            int kr = idx >> 5, n4 = (idx & 31) * 4;
            float4 wv = *(const float4*)(Wfc + (size_t)(kc + kr) * G + bn * 128 + n4);
            sB[kr * FBP + n4]     = f2tf(wv.x);
            sB[kr * FBP + n4 + 1] = f2tf(wv.y);
            sB[kr * FBP + n4 + 2] = f2tf(wv.z);
            sB[kr * FBP + n4 + 3] = f2tf(wv.w);
        }
        asm volatile("cp.async.wait_group 0;");
        __syncthreads();
        #pragma unroll
        for (int k0 = 0; k0 < 32; k0 += 8) {
            unsigned af[2][4], bf[8][2];
            #pragma unroll
            for (int mi = 0; mi < 2; mi++) {
                int row = wy * 32 + mi * 16;
                af[mi][0] = sA[(row + gq) * FAP + k0 + tq];
                af[mi][1] = sA[(row + gq + 8) * FAP + k0 + tq];
                af[mi][2] = sA[(row + gq) * FAP + k0 + tq + 4];
                af[mi][3] = sA[(row + gq + 8) * FAP + k0 + tq + 4];
            }
            #pragma unroll
            for (int ni = 0; ni < 8; ni++) {
                int c0 = wx * 64 + ni * 8;
                bf[ni][0] = sB[(k0 + tq) * FBP + c0 + gq];
                bf[ni][1] = sB[(k0 + tq + 4) * FBP + c0 + gq];
            }
            #pragma unroll
            for (int mi = 0; mi < 2; mi++)
                #pragma unroll
                for (int ni = 0; ni < 8; ni++)
                    mma8(acc[mi][ni], af[mi], bf[ni]);
        }
        __syncthreads();
    }
    #pragma unroll
    for (int mi = 0; mi < 2; mi++)
        #pragma unroll
        for (int ni = 0; ni < 8; ni++)
            #pragma unroll
            for (int e = 0; e < 4; e++) {
                int r  = bm * 128 + wy * 32 + mi * 16 + gq + (e >> 1) * 8;
                int cc = bn * 128 + wx * 64 + ni * 8 + 2 * tq + (e & 1);
                g_X[(size_t)r * G + cc] = acc[mi][ni][e] + bfc[cc];
            }
}

// ---------------- K4: fused hypergraph hops, 64-col blocks (R11 version, kept) ----------------
#define BP4 72     // B pitch (64 + 8)
#define SEP2 66    // E tile pitch (64 + 2)
#define FONE 0x3F800000u
#define AGG_SMEM ((192*6 + 192*6 + 2*16*BP4)*4 + (192 + 192 + 192*SEP2)*4)
__global__ void __launch_bounds__(256) k_agg_f() {
    extern __shared__ __align__(16) char asm_[];
    unsigned* sHw  = (unsigned*)asm_;                 // [edge][node-word]
    unsigned* sHT  = sHw + 192 * 6;                   // [node][edge-word]
    unsigned* sB   = sHT + 192 * 6;                   // hi | lo
    float*    sdegE = (float*)(sB + 2 * 16 * BP4);
    float*    sdegV = sdegE + 192;
    float*    sE   = sdegV + 192;                     // 192 x SEP2
    int d = blockIdx.y, n0 = blockIdx.x * 64;
    int tid = threadIdx.x, lane = tid & 31, warp = tid >> 5;
    int wy = warp >> 1, wx = warp & 1;        // wy: 48 rows, wx: 32 cols
    int gq = lane >> 2, tq = lane & 3;

    for (int i = tid; i < 192 * 6; i += 256) sHw[i] = g_H[(size_t)(d * M) * 6 + i];
    __syncthreads();

    // 32x32 bit-transpose blocks: 6x6 blocks over 8 warps
    for (int blk = warp; blk < 36; blk += 8) {
        int eb = blk / 6, nb = blk % 6;
        unsigned x = sHw[(eb * 32 + lane) * 6 + nb];
        #pragma unroll
        for (int i = 16; i >= 1; i >>= 1) {
            unsigned m = 0xFFFFFFFFu / ((1u << i) + 1u);
            unsigned y = __shfl_xor_sync(0xffffffffu, x, i);
            x = (lane & i) ? (((y >> i) & m) | (x & ~m))
                           : ((x & m) | ((y & m) << i));
        }
        sHT[(nb * 32 + lane) * 6 + eb] = x;
    }
    __syncthreads();

    if (tid < 192) {
        int dege = 0, degv = 0;
        #pragma unroll
        for (int w = 0; w < 6; w++) {
            dege += __popc(sHw[tid * 6 + w]);
            degv += __popc(sHT[tid * 6 + w]);
        }
        sdegE[tid] = 1.f / (float)dege;
        sdegV[tid] = 1.f / (float)degv;
    }

    float acc[3][4][4];
    #pragma unroll
    for (int mi = 0; mi < 3; mi++)
        #pragma unroll
        for (int ni = 0; ni < 4; ni++)
            #pragma unroll
            for (int e = 0; e < 4; e++) acc[mi][ni][e] = 0.f;

    int kr = tid >> 4, c4 = (tid & 15) * 4;   // 16 rows x 64 cols, float4/thread
    float4 nxt = *(const float4*)(g_X + (size_t)(d * M + kr) * G + n0 + c4);

    // ---- hop 0: E = (H @ X) / deg_e ----
    for (int kc = 0; kc < 192; kc += 16) {
        hilo(nxt.x, sB[kr * BP4 + c4],     sB[16 * BP4 + kr * BP4 + c4]);
        hilo(nxt.y, sB[kr * BP4 + c4 + 1], sB[16 * BP4 + kr * BP4 + c4 + 1]);
        hilo(nxt.z, sB[kr * BP4 + c4 + 2], sB[16 * BP4 + kr * BP4 + c4 + 2]);
        hilo(nxt.w, sB[kr * BP4 + c4 + 3], sB[16 * BP4 + kr * BP4 + c4 + 3]);
        __syncthreads();
        if (kc + 16 < 192)
            nxt = *(const float4*)(g_X + (size_t)(d * M + kc + 16 + kr) * G + n0 + c4);
        int kw = kc >> 5, sh = kc & 31;
        unsigned hw0[3], hw1[3];
        #pragma unroll
        for (int mi = 0; mi < 3; mi++) {
            int e0 = wy * 48 + mi * 16 + gq;
            hw0[mi] = sHw[e0 * 6 + kw];
            hw1[mi] = sHw[(e0 + 8) * 6 + kw];
        }
        #pragma unroll
        for (int k0 = 0; k0 < 16; k0 += 8) {
            unsigned af[3][4], bh[4][2], bl[4][2];
            int b0 = sh + k0 + tq;
            #pragma unroll
            for (int mi = 0; mi < 3; mi++) {
                af[mi][0] = ((hw0[mi] >> b0) & 1u)       ? FONE : 0u;
                af[mi][1] = ((hw1[mi] >> b0) & 1u)       ? FONE : 0u;
                af[mi][2] = ((hw0[mi] >> (b0 + 4)) & 1u) ? FONE : 0u;
                af[mi][3] = ((hw1[mi] >> (b0 + 4)) & 1u) ? FONE : 0u;
            }
            #pragma unroll
            for (int ni = 0; ni < 4; ni++) {
                int c0 = wx * 32 + ni * 8;
                bh[ni][0] = sB[(k0 + tq) * BP4 + c0 + gq];
                bh[ni][1] = sB[(k0 + tq + 4) * BP4 + c0 + gq];
                bl[ni][0] = sB[16 * BP4 + (k0 + tq) * BP4 + c0 + gq];
                bl[ni][1] = sB[16 * BP4 + (k0 + tq + 4) * BP4 + c0 + gq];
            }
            #pragma unroll
            for (int mi = 0; mi < 3; mi++)
                #pragma unroll
                for (int ni = 0; ni < 4; ni++) {
                    mma8(acc[mi][ni], af[mi], bh[ni]);
                    mma8(acc[mi][ni], af[mi], bl[ni]);
                }
        }
        __syncthreads();
    }
    #pragma unroll
    for (int mi = 0; mi < 3; mi++)
        #pragma unroll
        for (int ni = 0; ni < 4; ni++)
            #pragma unroll
            for (int e = 0; e < 4; e++) {
                int r = wy * 48 + mi * 16 + gq + (e >> 1) * 8;
                int c = wx * 32 + ni * 8 + 2 * tq + (e & 1);
                sE[r * SEP2 + c] = acc[mi][ni][e] * sdegE[r];
            }
    #pragma unroll
    for (int mi = 0; mi < 3; mi++)
        #pragma unroll
        for (int ni = 0; ni < 4; ni++)
            #pragma unroll
            for (int e = 0; e < 4; e++) acc[mi][ni][e] = 0.f;
    __syncthreads();

    // ---- hop 1: Y = (H^T @ E) / deg_v  (A bits from node-major sHT) ----
    for (int kc = 0; kc < 192; kc += 16) {
        float e0v = sE[(kc + kr) * SEP2 + c4];
        float e1v = sE[(kc + kr) * SEP2 + c4 + 1];
        float e2v = sE[(kc + kr) * SEP2 + c4 + 2];
        float e3v = sE[(kc + kr) * SEP2 + c4 + 3];
        hilo(e0v, sB[kr * BP4 + c4],     sB[16 * BP4 + kr * BP4 + c4]);
        hilo(e1v, sB[kr * BP4 + c4 + 1], sB[16 * BP4 + kr * BP4 + c4 + 1]);
        hilo(e2v, sB[kr * BP4 + c4 + 2], sB[16 * BP4 + kr * BP4 + c4 + 2]);
        hilo(e3v, sB[kr * BP4 + c4 + 3], sB[16 * BP4 + kr * BP4 + c4 + 3]);
        __syncthreads();
        int kw = kc >> 5, sh = kc & 31;
        unsigned ht0[3], ht1[3];
        #pragma unroll
        for (int mi = 0; mi < 3; mi++) {
            int nrow = wy * 48 + mi * 16 + gq;
            ht0[mi] = sHT[nrow * 6 + kw];
            ht1[mi] = sHT[(nrow + 8) * 6 + kw];
        }
        #pragma unroll
        for (int k0 = 0; k0 < 16; k0 += 8) {
            unsigned af[3][4], bh[4][2], bl[4][2];
            int b0 = sh + k0 + tq;
            #pragma unroll
            for (int mi = 0; mi < 3; mi++) {
                af[mi][0] = ((ht0[mi] >> b0) & 1u)       ? FONE : 0u;
                af[mi][1] = ((ht1[mi] >> b0) & 1u)       ? FONE : 0u;
                af[mi][2] = ((ht0[mi] >> (b0 + 4)) & 1u) ? FONE : 0u;
                af[mi][3] = ((ht1[mi] >> (b0 + 4)) & 1u) ? FONE : 0u;
            }
            #pragma unroll
            for (int ni = 0; ni < 4; ni++) {
                int c0 = wx * 32 + ni * 8;
                bh[ni][0] = sB[(k0 + tq) * BP4 + c0 + gq];
                bh[ni][1] = sB[(k0 + tq + 4) * BP4 + c0 + gq];
                bl[ni][0] = sB[16 * BP4 + (k0 + tq) * BP4 + c0 + gq];
                bl[ni][1] = sB[16 * BP4 + (k0 + tq + 4) * BP4 + c0 + gq];
            }
            #pragma unroll
            for (int mi = 0; mi < 3; mi++)
                #pragma unroll
                for (int ni = 0; ni < 4; ni++) {
                    mma8(acc[mi][ni], af[mi], bh[ni]);
                    mma8(acc[mi][ni], af[mi], bl[ni]);
                }
        }
        __syncthreads();
    }
    #pragma unroll
    for (int mi = 0; mi < 3; mi++)
        #pragma unroll
        for (int ni = 0; ni < 4; ni++)
            #pragma unroll
            for (int e = 0; e < 4; e++) {
                int r = wy * 48 + mi * 16 + gq + (e >> 1) * 8;
                int c = n0 + wx * 32 + ni * 8 + 2 * tq + (e & 1);
                g_Y[(size_t)(d * M + r) * G + c] = acc[mi][ni][e] * sdegV[r];
            }
}

// ---------------- K6: out = relu(Y @ W_h + b_h) (tf32 mma), regrouped ----------------
__global__ void __launch_bounds__(256) k_out_mma(const float* Wh, const float* bh,
                                                 float* out) {
    __shared__ unsigned sA[128 * FAP];
    __shared__ unsigned sB[32 * FBP];
    int bn = blockIdx.x, bm = blockIdx.y;
    int tid = threadIdx.x, lane = tid & 31, warp = tid >> 5;
    int wy = warp >> 1, wx = warp & 1;
    int gq = lane >> 2, tq = lane & 3;

    float acc[2][8][4];
    #pragma unroll
    for (int mi = 0; mi < 2; mi++)
        #pragma unroll
        for (int ni = 0; ni < 8; ni++)
            #pragma unroll
            for (int e = 0; e < 4; e++) acc[mi][ni][e] = 0.f;

    for (int kc = 0; kc < G; kc += 32) {
        #pragma unroll
        for (int it = 0; it < 4; it++) {
            int idx = tid + it * 256;
            int r = idx >> 3, c = (idx & 7) * 4;
            float4 xv = *(const float4*)(g_Y + (size_t)(bm * 128 + r) * G + kc + c);
            sA[r * FAP + c]     = f2tf(xv.x);
            sA[r * FAP + c + 1] = f2tf(xv.y);
            sA[r * FAP + c + 2] = f2tf(xv.z);
            sA[r * FAP + c + 3] = f2tf(xv.w);
        }
        #pragma unroll
        for (int it = 0; it < 4; it++) {
            int idx = tid + it * 256;
            int kr = idx >> 5, n4 = (idx & 31) * 4;
            float4 wv = *(const float4*)(Wh + (size_t)(kc + kr) * G + bn * 128 + n4);
            sB[kr * FBP + n4]     = f2tf(wv.x);
            sB[kr * FBP + n4 + 1] = f2tf(wv.y);
            sB[kr * FBP + n4 + 2] = f2tf(wv.z);
            sB[kr * FBP + n4 + 3] = f2tf(wv.w);
        }
        __syncthreads();
        #pragma unroll
        for (int k0 = 0; k0 < 32; k0 += 8) {
            unsigned af[2][4], bf[8][2];
            #pragma unroll
            for (int mi = 0; mi < 2; mi++) {
                int row = wy * 32 + mi * 16;
                af[mi][0] = sA[(row + gq) * FAP + k0 + tq];
                af[mi][1] = sA[(row + gq + 8) * FAP + k0 + tq];
                af[mi][2] = sA[(row + gq) * FAP + k0 + tq + 4];
                af[mi][3] = sA[(row + gq + 8) * FAP + k0 + tq + 4];
            }
            #pragma unroll
            for (int ni = 0; ni < 8; ni++) {
                int c0 = wx * 64 + ni * 8;
                bf[ni][0] = sB[(k0 + tq) * FBP + c0 + gq];
                bf[ni][1] = sB[(k0 + tq + 4) * FBP + c0 + gq];
            }
            #pragma unroll
            for (int mi = 0; mi < 2; mi++)
                #pragma unroll
                for (int ni = 0; ni < 8; ni++)
                    mma8(acc[mi][ni], af[mi], bf[ni]);
        }
        __syncthreads();
    }
    #pragma unroll
    for (int mi = 0; mi < 2; mi++)
        #pragma unroll
        for (int ni = 0; ni < 8; ni++)
            #pragma unroll
            for (int e = 0; e < 4; e++) {
                int gn = bm * 128 + wy * 32 + mi * 16 + gq + (e >> 1) * 8;
                int gc = bn * 128 + wx * 64 + ni * 8 + 2 * tq + (e & 1);
                int dd = gn / M, n = gn % M, mod = n >> 6, ii = n & 63;
                out[(size_t)(dd * L + ii) * 768 + mod * 256 + gc] =
                    fmaxf(acc[mi][ni][e] + bh[gc], 0.f);
            }
}

// ---------------- K7: norms, diag sims, zero LSE accumulators, bf16 convert ----------------
__global__ void k_norm(const float* out) {
    int i = blockIdx.x;
    int tid = threadIdx.x;
    float tv = out[(size_t)i * 768 + tid];
    float av = out[(size_t)i * 768 + 256 + tid];
    float vv = out[(size_t)i * 768 + 512 + tid];
    float q[6] = { tv * tv, av * av, vv * vv, tv * av, tv * vv, av * vv };
    __shared__ float red[6][8];
    __shared__ float sinv[3];
    int lane = tid & 31, w = tid >> 5;
    #pragma unroll
    for (int o = 16; o; o >>= 1)
        #pragma unroll
        for (int k = 0; k < 6; k++) q[k] += __shfl_down_sync(0xffffffffu, q[k], o);
    if (lane == 0)
        #pragma unroll
        for (int k = 0; k < 6; k++) red[k][w] = q[k];
    __syncthreads();
    if (tid == 0) {
        float s[6];
        #pragma unroll
        for (int k = 0; k < 6; k++) {
            s[k] = 0.f;
            #pragma unroll
            for (int w2 = 0; w2 < 8; w2++) s[k] += red[k][w2];
        }
        float it = 1.f / (sqrtf(s[0]) + 1e-8f);
        float ia = 1.f / (sqrtf(s[1]) + 1e-8f);
        float iv = 1.f / (sqrtf(s[2]) + 1e-8f);
        sinv[0] = it * SQTAUI; sinv[1] = ia * SQTAUI; sinv[2] = iv * SQTAUI;
        g_diag[i]             = s[3] * it * ia * TAUINV;
        g_diag[NROWS + i]     = s[4] * it * iv * TAUINV;
        g_diag[2 * NROWS + i] = s[5] * ia * iv * TAUINV;
        g_rowsum[i] = 0.f; g_rowsum[NROWS + i] = 0.f; g_rowsum[2 * NROWS + i] = 0.f;
        g_colsum[i] = 0.f; g_colsum[NROWS + i] = 0.f; g_colsum[2 * NROWS + i] = 0.f;
    }
    __syncthreads();
    g_nb[((size_t)0 * NROWS + i) * G + tid] = __float2bfloat16(tv * sinv[0]);
    g_nb[((size_t)1 * NROWS + i) * G + tid] = __float2bfloat16(av * sinv[1]);
    g_nb[((size_t)2 * NROWS + i) * G + tid] = __float2bfloat16(vv * sinv[2]);
}

// ---------------- K8: bf16 sim tiles; X panel resident, 4 col tiles per block ----------------
#define SPITCH 40
#define XPITCH 264
#define SIM_SMEM (128*XPITCH*2 + 2*128*SPITCH*2 + 256*4)
__global__ void __launch_bounds__(256) k_sim_mma() {
    extern __shared__ __align__(16) char dsm[];
    __nv_bfloat16* sXp = (__nv_bfloat16*)dsm;                       // 128 x 256 panel
    __nv_bfloat16* sY  = sXp + 128 * XPITCH;                         // 2 x 128 x SPITCH
    float* srow = (float*)(sY + 2 * 128 * SPITCH);
    float* scol = srow + 128;

    int p = blockIdx.z;
    int mx = (p == 2) ? 1 : 0;
    int my = (p == 0) ? 1 : 2;
    int row0 = blockIdx.y * 128;
    int tid = threadIdx.x, lane = tid & 31, warp = tid >> 5;
    int wy = warp >> 1, wx = warp & 1;      // warp tile: 32 rows x 64 cols

    const __nv_bfloat16* xg = g_nb + ((size_t)mx * NROWS + row0) * G;

    #pragma unroll
    for (int it = 0; it < 16; it++) {
        int idx = tid + it * 256;
        int r = idx >> 5, c = (idx & 31) * 8;
        cp16(sXp + r * XPITCH + c, xg + (size_t)r * G + c);
    }
    cp_commit();
    asm volatile("cp.async.wait_group 0;");
    __syncthreads();

    int lr = tid >> 2, lc = (tid & 3) * 8;
    int lr2 = lr + 64;

    for (int j = 0; j < 4; j++) {
        int col0 = (blockIdx.x * 4 + j) * 128;
        const __nv_bfloat16* yg = g_nb + ((size_t)my * NROWS + col0) * G;

        float acc[2][8][4];
        #pragma unroll
        for (int mi = 0; mi < 2; mi++)
            #pragma unroll
            for (int ni = 0; ni < 8; ni++)
                #pragma unroll
                for (int r = 0; r < 4; r++) acc[mi][ni][r] = 0.f;

        cp16(sY + lr * SPITCH + lc,  yg + (size_t)lr * G + lc);
        cp16(sY + lr2 * SPITCH + lc, yg + (size_t)lr2 * G + lc);
        cp_commit();

        #pragma unroll
        for (int c = 0; c < 8; c++) {
            int cur = c & 1;
            if (c < 7) {
                int nb = (c + 1) & 1, kc2 = (c + 1) * 32;
                cp16(sY + nb * 128 * SPITCH + lr * SPITCH + lc,
                     yg + (size_t)lr * G + kc2 + lc);
                cp16(sY + nb * 128 * SPITCH + lr2 * SPITCH + lc,
                     yg + (size_t)lr2 * G + kc2 + lc);
                cp_commit();
                asm volatile("cp.async.wait_group 1;");
            } else {
                asm volatile("cp.async.wait_group 0;");
            }
            __syncthreads();
            int kc = c * 32;
            #pragma unroll
            for (int ks = 0; ks < 2; ks++) {
                int k0 = ks * 16;
                unsigned A[2][4];
                #pragma unroll
                for (int mi = 0; mi < 2; mi++) {
                    int r = wy * 32 + mi * 16 + ((lane >> 3) & 1) * 8 + (lane & 7);
                    int cc = kc + k0 + (lane >> 4) * 8;
                    unsigned ad = (unsigned)__cvta_generic_to_shared(sXp + r * XPITCH + cc);
                    asm volatile("ldmatrix.sync.aligned.m8n8.x4.shared.b16 {%0,%1,%2,%3},[%4];"
                        : "=r"(A[mi][0]), "=r"(A[mi][1]), "=r"(A[mi][2]), "=r"(A[mi][3])
                        : "r"(ad));
                }
                unsigned B[8][2];
                #pragma unroll
                for (int nb2 = 0; nb2 < 4; nb2++) {
                    int r = wx * 64 + nb2 * 16 + (lane >> 4) * 8 + (lane & 7);
                    int cc = k0 + ((lane >> 3) & 1) * 8;
                    unsigned ad = (unsigned)__cvta_generic_to_shared(
                        sY + cur * 128 * SPITCH + r * SPITCH + cc);
                    asm volatile("ldmatrix.sync.aligned.m8n8.x4.shared.b16 {%0,%1,%2,%3},[%4];"
                        : "=r"(B[2 * nb2][0]), "=r"(B[2 * nb2][1]),
                          "=r"(B[2 * nb2 + 1][0]), "=r"(B[2 * nb2 + 1][1])
                        : "r"(ad));
                }
                #pragma unroll
                for (int mi = 0; mi < 2; mi++)
                    #pragma unroll
                    for (int ni = 0; ni < 8; ni++)
                        asm volatile(
                            "mma.sync.aligned.m16n8k16.row.col.f32.bf16.bf16.f32 "
                            "{%0,%1,%2,%3},{%4,%5,%6,%7},{%8,%9},{%0,%1,%2,%3};"
                            : "+f"(acc[mi][ni][0]), "+f"(acc[mi][ni][1]),
                              "+f"(acc[mi][ni][2]), "+f"(acc[mi][ni][3])
                            : "r"(A[mi][0]), "r"(A[mi][1]), "r"(A[mi][2]), "r"(A[mi][3]),
                              "r"(B[ni][0]), "r"(B[ni][1]));
            }
            __syncthreads();
        }

        if (tid < 128) { srow[tid] = 0.f; scol[tid] = 0.f; }
        __syncthreads();

        float rowp[2][2] = {{0.f, 0.f}, {0.f, 0.f}};
        float colp[8][2];
        #pragma unroll
        for (int ni = 0; ni < 8; ni++) { colp[ni][0] = 0.f; colp[ni][1] = 0.f; }
        #pragma unroll
        for (int mi = 0; mi < 2; mi++)
            #pragma unroll
            for (int ni = 0; ni < 8; ni++)
                #pragma unroll
                for (int r = 0; r < 4; r++) {
                    float e = __expf(acc[mi][ni][r]);
                    rowp[mi][r >> 1] += e;
                    colp[ni][r & 1] += e;
                }

        #pragma unroll
        for (int mi = 0; mi < 2; mi++)
            #pragma unroll
            for (int h = 0; h < 2; h++) {
                float vv = rowp[mi][h];
                vv += __shfl_xor_sync(0xffffffffu, vv, 1);
                vv += __shfl_xor_sync(0xffffffffu, vv, 2);
                if ((lane & 3) == 0)
                    atomicAdd(&srow[wy * 32 + mi * 16 + (lane >> 2) + h * 8], vv);
            }
        #pragma unroll
        for (int ni = 0; ni < 8; ni++)
            #pragma unroll
            for (int s2 = 0; s2 < 2; s2++) {
                float vv = colp[ni][s2];
                vv += __shfl_xor_sync(0xffffffffu, vv, 4);
                vv += __shfl_xor_sync(0xffffffffu, vv, 8);
                vv += __shfl_xor_sync(0xffffffffu, vv, 16);
                if (lane < 4)
                    atomicAdd(&scol[wx * 64 + ni * 8 + lane * 2 + s2], vv);
            }
        __syncthreads();
        if (tid < 128) {
            atomicAdd(&g_rowsum[p * NROWS + row0 + tid], srow[tid]);
            atomicAdd(&g_colsum[p * NROWS + col0 + tid], scol[tid]);
        }
        __syncthreads();
    }
}

// ---------------- K9: final loss reduction ----------------
__global__ void k_loss(float* out, int out_size) {
    int tid = threadIdx.x;
    float s = 0.f;
    for (int idx = tid; idx < 3 * NROWS; idx += 256) {
        float dg = g_diag[idx];
        s += 2.f * dg - logf(g_rowsum[idx]) - logf(g_colsum[idx]);
    }
    __shared__ float red[8];
    int lane = tid & 31, w = tid >> 5;
    #pragma unroll
    for (int o = 16; o; o >>= 1) s += __shfl_down_sync(0xffffffffu, s, o);
    if (lane == 0) red[w] = s;
    __syncthreads();
    if (tid == 0) {
        float tot = 0.f;
        #pragma unroll
        for (int w2 = 0; w2 < 8; w2++) tot += red[w2];
        float loss = -tot / (2.f * 3.f * (float)NROWS);
        if (out_size > NROWS * 768) out[NROWS * 768] = loss;
    }
}

// ---------------- launcher ----------------
extern "C" void kernel_launch(void* const* d_in, const int* in_sizes, int n_in,
                              void* d_out, int out_size) {
    const float* t   = (const float*)d_in[0];
    const float* a   = (const float*)d_in[1];
    const float* v   = (const float*)d_in[2];
    const float* Wfc = (const float*)d_in[3];
    const float* bfc = (const float*)d_in[4];
    const float* Wh  = (const float*)d_in[5];
    const float* bh  = (const float*)d_in[6];
    float* out = (float*)d_out;

    cudaFuncSetAttribute(k_sim_mma,
        cudaFuncAttributeMaxDynamicSharedMemorySize, SIM_SMEM);
    cudaFuncSetAttribute(k_agg_f,
        cudaFuncAttributeMaxDynamicSharedMemorySize, AGG_SMEM);

    k_sq<<<NNODE / 8, 256>>>(t, a, v);
    k_gram_mma<<<dim3(6, 64), 256>>>();
    k_fc_mma<<<dim3(2, 96), 256>>>(Wfc, bfc);
    k_agg_f<<<dim3(4, 64), 256, AGG_SMEM>>>();
    k_out_mma<<<dim3(2, 96), 256>>>(Wh, bh, out);
    k_norm<<<NROWS, 256>>>(out);
    k_sim_mma<<<dim3(8, 32, 3), 256, SIM_SMEM>>>();
    k_loss<<<1, 256>>>(out, out_size);
}

// round 13
// speedup vs baseline: 1.1518x; 1.0047x over previous
#include <cuda_runtime.h>
#include <cuda_bf16.h>
#include <math.h>
#include <float.h>

#define D 64
#define L 64
#define DIMF 512
#define G 256
#define M 192                 // 3*L nodes (= hyperedges) per dialogue
#define KTOP 12
#define NROWS 4096            // D*L
#define NNODE (D*M)           // 12288
#define TAUINV (1.0f/0.07f)
#define SQTAUI 3.7796447300922722f   // sqrt(1/0.07)

// ---- scratch (static device arrays; no allocation allowed) ----
__device__ float    g_sq[NNODE];
__device__ unsigned g_fh[(size_t)NNODE*DIMF];   // tf32 hi of features
__device__ unsigned g_fl[(size_t)NNODE*DIMF];   // tf32 lo of features
__device__ unsigned g_H[NNODE*6];       // 192-bit incidence mask per edge
__device__ float    g_X[NNODE*G];
__device__ float    g_Y[NNODE*G];
__device__ float    g_diag[3*NROWS];
__device__ float    g_rowsum[3*NROWS];
__device__ float    g_colsum[3*NROWS];
__device__ __nv_bfloat16 g_nb[(size_t)3*NROWS*G];   // normalized bf16 features (loss path only)

__device__ __forceinline__ const float* feat_row(int d, int n,
        const float* t, const float* a, const float* v) {
    int mod = n >> 6, i = n & 63;
    const float* base = (mod == 0) ? t : (mod == 1) ? a : v;
    return base + (size_t)(d * L + i) * DIMF;
}

// ---- tf32 helpers ----
__device__ __forceinline__ unsigned f2tf(float x) {
    unsigned u; asm("cvt.rna.tf32.f32 %0, %1;" : "=r"(u) : "f"(x)); return u;
}
__device__ __forceinline__ void hilo(float x, unsigned& h, unsigned& l) {
    h = f2tf(x);
    l = f2tf(x - __uint_as_float(h));
}
__device__ __forceinline__ void mma8(float* c, const unsigned* a, const unsigned* b) {
    asm volatile("mma.sync.aligned.m16n8k8.row.col.f32.tf32.tf32.f32 "
        "{%0,%1,%2,%3},{%4,%5,%6,%7},{%8,%9},{%0,%1,%2,%3};"
        : "+f"(c[0]), "+f"(c[1]), "+f"(c[2]), "+f"(c[3])
        : "r"(a[0]), "r"(a[1]), "r"(a[2]), "r"(a[3]), "r"(b[0]), "r"(b[1]));
}

// ---- cp.async helpers ----
__device__ __forceinline__ void cp16(void* dst_smem, const void* src) {
    unsigned ad = (unsigned)__cvta_generic_to_shared(dst_smem);
    asm volatile("cp.async.cg.shared.global [%0],[%1],16;" :: "r"(ad), "l"(src));
}
__device__ __forceinline__ void cp_commit() {
    asm volatile("cp.async.commit_group;");
}

// ---------------- K1: per-node squared norms + hi/lo precompute ----------------
__global__ void k_sq(const float* t, const float* a, const float* v) {
    int warp = (blockIdx.x * blockDim.x + threadIdx.x) >> 5;
    int lane = threadIdx.x & 31;
    if (warp >= NNODE) return;
    int d = warp / M, n = warp % M;
    const float* r = feat_row(d, n, t, a, v);
    float s = 0.f;
    #pragma unroll
    for (int c = lane; c < DIMF; c += 32) { float x = r[c]; s += x * x; }
    unsigned* fh = g_fh + (size_t)warp * DIMF;
    unsigned* fl = g_fl + (size_t)warp * DIMF;
    #pragma unroll
    for (int c0 = lane * 4; c0 < DIMF; c0 += 128) {
        float4 x = *(const float4*)(r + c0);
        uint4 h, l;
        hilo(x.x, h.x, l.x); hilo(x.y, h.y, l.y);
        hilo(x.z, h.z, l.z); hilo(x.w, h.w, l.w);
        *(uint4*)(fh + c0) = h;
        *(uint4*)(fl + c0) = l;
    }
    #pragma unroll
    for (int o = 16; o; o >>= 1) s += __shfl_down_sync(0xffffffffu, s, o);
    if (lane == 0) g_sq[warp] = s;
}

// ---------------- K2: 3xTF32 gram, double-buffered cp.async pipeline ----------------
#define GBP2 20
#define GRAM_SMEM (2 * 2 * 192 * GBP2 * 4 + M * 4)
__global__ void __launch_bounds__(256) k_gram_mma() {
    extern __shared__ __align__(16) char gsm[];
    unsigned* Bbuf0 = (unsigned*)gsm;                 // buffer 0: hi | lo
    unsigned* Bbuf1 = Bbuf0 + 2 * 192 * GBP2;         // buffer 1: hi | lo
    float* sq = (float*)(Bbuf1 + 2 * 192 * GBP2);

    int d = blockIdx.y, i0 = blockIdx.x * 32;
    int tid = threadIdx.x, lane = tid & 31, warp = tid >> 5;
    int gq = lane >> 2, tq = lane & 3;
    if (tid < M) sq[tid] = g_sq[d * M + tid];
    size_t base = (size_t)(d * M) * DIMF;

    // per-thread load indices: 3 iterations of 256 threads cover 768 quads
    int ln[3], lk[3];
    #pragma unroll
    for (int it = 0; it < 3; it++) {
        int idx = tid + it * 256;
        ln[it] = idx >> 2; lk[it] = (idx & 3) * 4;
    }

    float acc[2][3][4];
    #pragma unroll
    for (int mi = 0; mi < 2; mi++)
        #pragma unroll
        for (int ni = 0; ni < 3; ni++)
            #pragma unroll
            for (int e = 0; e < 4; e++) acc[mi][ni][e] = 0.f;

    // prologue: chunk 0 into buffer 0
    #pragma unroll
    for (int it = 0; it < 3; it++) {
        cp16(Bbuf0 + ln[it] * GBP2 + lk[it],
             g_fh + base + (size_t)ln[it] * DIMF + lk[it]);
        cp16(Bbuf0 + 192 * GBP2 + ln[it] * GBP2 + lk[it],
             g_fl + base + (size_t)ln[it] * DIMF + lk[it]);
    }
    cp_commit();

    for (int c = 0; c < 32; c++) {
        if (c < 31) {
            unsigned* nb = (c & 1) ? Bbuf0 : Bbuf1;   // (c+1)&1 buffer
            int kc2 = (c + 1) * 16;
            #pragma unroll
            for (int it = 0; it < 3; it++) {
                cp16(nb + ln[it] * GBP2 + lk[it],
                     g_fh + base + (size_t)ln[it] * DIMF + kc2 + lk[it]);
                cp16(nb + 192 * GBP2 + ln[it] * GBP2 + lk[it],
                     g_fl + base + (size_t)ln[it] * DIMF + kc2 + lk[it]);
            }
            cp_commit();
            asm volatile("cp.async.wait_group 1;");
        } else {
            asm volatile("cp.async.wait_group 0;");
        }
        __syncthreads();
        unsigned* Bhi = (c & 1) ? Bbuf1 : Bbuf0;
        unsigned* Blo = Bhi + 192 * GBP2;
        #pragma unroll
        for (int k0 = 0; k0 < 16; k0 += 8) {
            unsigned ah[2][4], al[2][4], bh[3][2], bl[3][2];
            #pragma unroll
            for (int mi = 0; mi < 2; mi++) {
                int r0 = (i0 + mi * 16 + gq) * GBP2;
                int r1 = r0 + 8 * GBP2;
                ah[mi][0] = Bhi[r0 + k0 + tq];
                ah[mi][1] = Bhi[r1 + k0 + tq];
                ah[mi][2] = Bhi[r0 + k0 + tq + 4];
                ah[mi][3] = Bhi[r1 + k0 + tq + 4];
                al[mi][0] = Blo[r0 + k0 + tq];
                al[mi][1] = Blo[r1 + k0 + tq];
                al[mi][2] = Blo[r0 + k0 + tq + 4];
                al[mi][3] = Blo[r1 + k0 + tq + 4];
            }
            #pragma unroll
            for (int ni = 0; ni < 3; ni++) {
                int c0 = (warp * 24 + ni * 8 + gq) * GBP2;
                bh[ni][0] = Bhi[c0 + k0 + tq];
                bh[ni][1] = Bhi[c0 + k0 + tq + 4];
                bl[ni][0] = Blo[c0 + k0 + tq];
                bl[ni][1] = Blo[c0 + k0 + tq + 4];
            }
            #pragma unroll
            for (int mi = 0; mi < 2; mi++)
                #pragma unroll
                for (int ni = 0; ni < 3; ni++) {
                    mma8(acc[mi][ni], ah[mi], bh[ni]);
                    mma8(acc[mi][ni], ah[mi], bl[ni]);
                    mma8(acc[mi][ni], al[mi], bh[ni]);
                }
        }
        __syncthreads();
    }

    float* d2s = (float*)Bbuf0;
    #pragma unroll
    for (int mi = 0; mi < 2; mi++)
        #pragma unroll
        for (int ni = 0; ni < 3; ni++)
            #pragma unroll
            for (int e = 0; e < 4; e++) {
                int r = mi * 16 + gq + (e >> 1) * 8;
                int c = warp * 24 + ni * 8 + 2 * tq + (e & 1);
                float v2 = sq[i0 + r] + sq[c] - 2.f * acc[mi][ni][e];
                d2s[r * 192 + c] = fmaxf(v2, 0.f);
            }
    __syncthreads();

    int tx = lane;
    for (int q = 0; q < 4; q++) {
        int r = warp * 4 + q;
        float val[6];
        #pragma unroll
        for (int s = 0; s < 6; s++) val[s] = d2s[r * 192 + tx + 32 * s];
        unsigned mask[6] = {0, 0, 0, 0, 0, 0};
        for (int pick = 0; pick < KTOP; pick++) {
            float bv = val[0]; int bi = tx;
            #pragma unroll
            for (int s = 1; s < 6; s++) {
                float vv = val[s];
                if (vv < bv) { bv = vv; bi = tx + 32 * s; }
            }
            #pragma unroll
            for (int o = 16; o; o >>= 1) {
                float ov = __shfl_down_sync(0xffffffffu, bv, o);
                int   oi = __shfl_down_sync(0xffffffffu, bi, o);
                if (ov < bv || (ov == bv && oi < bi)) { bv = ov; bi = oi; }
            }
            bi = __shfl_sync(0xffffffffu, bi, 0);
            if ((bi & 31) == tx) val[bi >> 5] = FLT_MAX;
            mask[bi >> 5] |= 1u << (bi & 31);
        }
        if (tx == 0) {
            int e = i0 + r;
            int u = e / 3;
            mask[u >> 5]           |= 1u << (u & 31);
            mask[(u + 64) >> 5]    |= 1u << ((u + 64) & 31);
            mask[(u + 128) >> 5]   |= 1u << ((u + 128) & 31);
            #pragma unroll
            for (int w = 0; w < 6; w++)
                g_H[(size_t)(d * M + e) * 6 + w] = mask[w];
        }
    }
}

// ---------------- K3: X = feat @ W_fc + b_fc  (tf32 mma, 128x128 tile) ----------------
#define FAP 36
#define FBP 136
__global__ void __launch_bounds__(256) k_fc_mma(const float* Wfc, const float* bfc) {
    __shared__ unsigned sA[128 * FAP];
    __shared__ unsigned sB[32 * FBP];
    int bn = blockIdx.x, bm = blockIdx.y;
    int tid = threadIdx.x, lane = tid & 31, warp = tid >> 5;
    int wy = warp >> 1, wx = warp & 1;
    int gq = lane >> 2, tq = lane & 3;

    float acc[2][8][4];
    #pragma unroll
    for (int mi = 0; mi < 2; mi++)
        #pragma unroll
        for (int ni = 0; ni < 8; ni++)
            #pragma unroll
            for (int e = 0; e < 4; e++) acc[mi][ni][e] = 0.f;

    for (int kc = 0; kc < DIMF; kc += 32) {
        #pragma unroll
        for (int it = 0; it < 4; it++) {
            int idx = tid + it * 256;
            int r = idx >> 3, c = (idx & 7) * 4;
            cp16(sA + r * FAP + c, g_fh + (size_t)(bm * 128 + r) * DIMF + kc + c);
        }
        cp_commit();
        #pragma unroll
        for (int it = 0; it < 4; it++) {
            int idx = tid + it * 256;
            int kr = idx >> 5, n4 = (idx & 31) * 4;
            float4 wv = *(const float4*)(Wfc + (size_t)(kc + kr) * G + bn * 128 + n4);
            sB[kr * FBP + n4]     = f2tf(wv.x);
            sB[kr * FBP + n4 + 1] = f2tf(wv.y);
            sB[kr * FBP + n4 + 2] = f2tf(wv.z);
            sB[kr * FBP + n4 + 3] = f2tf(wv.w);
        }
        asm volatile("cp.async.wait_group 0;");
        __syncthreads();
        #pragma unroll
        for (int k0 = 0; k0 < 32; k0 += 8) {
            unsigned af[2][4], bf[8][2];
            #pragma unroll
            for (int mi = 0; mi < 2; mi++) {
                int row = wy * 32 + mi * 16;
                af[mi][0] = sA[(row + gq) * FAP + k0 + tq];
                af[mi][1] = sA[(row + gq + 8) * FAP + k0 + tq];
                af[mi][2] = sA[(row + gq) * FAP + k0 + tq + 4];
                af[mi][3] = sA[(row + gq + 8) * FAP + k0 + tq + 4];
            }
            #pragma unroll
            for (int ni = 0; ni < 8; ni++) {
                int c0 = wx * 64 + ni * 8;
                bf[ni][0] = sB[(k0 + tq) * FBP + c0 + gq];
                bf[ni][1] = sB[(k0 + tq + 4) * FBP + c0 + gq];
            }
            #pragma unroll
            for (int mi = 0; mi < 2; mi++)
                #pragma unroll
                for (int ni = 0; ni < 8; ni++)
                    mma8(acc[mi][ni], af[mi], bf[ni]);
        }
        __syncthreads();
    }
    #pragma unroll
    for (int mi = 0; mi < 2; mi++)
        #pragma unroll
        for (int ni = 0; ni < 8; ni++)
            #pragma unroll
            for (int e = 0; e < 4; e++) {
                int r  = bm * 128 + wy * 32 + mi * 16 + gq + (e >> 1) * 8;
                int cc = bn * 128 + wx * 64 + ni * 8 + 2 * tq + (e & 1);
                g_X[(size_t)r * G + cc] = acc[mi][ni][e] + bfc[cc];
            }
}

// ---------------- K4: fused hypergraph hops, 64-col blocks ----------------
#define BP4 72     // B pitch (64 + 8)
#define SEP2 66    // E tile pitch (64 + 2)
#define FONE 0x3F800000u
#define AGG_SMEM ((192*6 + 192*6 + 2*16*BP4)*4 + (192 + 192 + 192*SEP2)*4)
__global__ void __launch_bounds__(256) k_agg_f() {
    extern __shared__ __align__(16) char asm_[];
    unsigned* sHw  = (unsigned*)asm_;                 // [edge][node-word]
    unsigned* sHT  = sHw + 192 * 6;                   // [node][edge-word]
    unsigned* sB   = sHT + 192 * 6;                   // hi | lo
    float*    sdegE = (float*)(sB + 2 * 16 * BP4);
    float*    sdegV = sdegE + 192;
    float*    sE   = sdegV + 192;                     // 192 x SEP2
    int d = blockIdx.y, n0 = blockIdx.x * 64;
    int tid = threadIdx.x, lane = tid & 31, warp = tid >> 5;
    int wy = warp >> 1, wx = warp & 1;        // wy: 48 rows, wx: 32 cols
    int gq = lane >> 2, tq = lane & 3;

    for (int i = tid; i < 192 * 6; i += 256) sHw[i] = g_H[(size_t)(d * M) * 6 + i];
    __syncthreads();

    // 32x32 bit-transpose blocks: 6x6 blocks over 8 warps
    for (int blk = warp; blk < 36; blk += 8) {
        int eb = blk / 6, nb = blk % 6;
        unsigned x = sHw[(eb * 32 + lane) * 6 + nb];
        #pragma unroll
        for (int i = 16; i >= 1; i >>= 1) {
            unsigned m = 0xFFFFFFFFu / ((1u << i) + 1u);
            unsigned y = __shfl_xor_sync(0xffffffffu, x, i);
            x = (lane & i) ? (((y >> i) & m) | (x & ~m))
                           : ((x & m) | ((y & m) << i));
        }
        sHT[(nb * 32 + lane) * 6 + eb] = x;
    }
    __syncthreads();

    if (tid < 192) {
        int dege = 0, degv = 0;
        #pragma unroll
        for (int w = 0; w < 6; w++) {
            dege += __popc(sHw[tid * 6 + w]);
            degv += __popc(sHT[tid * 6 + w]);
        }
        sdegE[tid] = 1.f / (float)dege;
        sdegV[tid] = 1.f / (float)degv;
    }

    float acc[3][4][4];
    #pragma unroll
    for (int mi = 0; mi < 3; mi++)
        #pragma unroll
        for (int ni = 0; ni < 4; ni++)
            #pragma unroll
            for (int e = 0; e < 4; e++) acc[mi][ni][e] = 0.f;

    int kr = tid >> 4, c4 = (tid & 15) * 4;   // 16 rows x 64 cols, float4/thread
    float4 nxt = *(const float4*)(g_X + (size_t)(d * M + kr) * G + n0 + c4);

    // ---- hop 0: E = (H @ X) / deg_e ----
    for (int kc = 0; kc < 192; kc += 16) {
        hilo(nxt.x, sB[kr * BP4 + c4],     sB[16 * BP4 + kr * BP4 + c4]);
        hilo(nxt.y, sB[kr * BP4 + c4 + 1], sB[16 * BP4 + kr * BP4 + c4 + 1]);
        hilo(nxt.z, sB[kr * BP4 + c4 + 2], sB[16 * BP4 + kr * BP4 + c4 + 2]);
        hilo(nxt.w, sB[kr * BP4 + c4 + 3], sB[16 * BP4 + kr * BP4 + c4 + 3]);
        __syncthreads();
        if (kc + 16 < 192)
            nxt = *(const float4*)(g_X + (size_t)(d * M + kc + 16 + kr) * G + n0 + c4);
        int kw = kc >> 5, sh = kc & 31;
        unsigned hw0[3], hw1[3];
        #pragma unroll
        for (int mi = 0; mi < 3; mi++) {
            int e0 = wy * 48 + mi * 16 + gq;
            hw0[mi] = sHw[e0 * 6 + kw];
            hw1[mi] = sHw[(e0 + 8) * 6 + kw];
        }
        #pragma unroll
        for (int k0 = 0; k0 < 16; k0 += 8) {
            unsigned af[3][4], bh[4][2], bl[4][2];
            int b0 = sh + k0 + tq;
            #pragma unroll
            for (int mi = 0; mi < 3; mi++) {
                af[mi][0] = ((hw0[mi] >> b0) & 1u)       ? FONE : 0u;
                af[mi][1] = ((hw1[mi] >> b0) & 1u)       ? FONE : 0u;
                af[mi][2] = ((hw0[mi] >> (b0 + 4)) & 1u) ? FONE : 0u;
                af[mi][3] = ((hw1[mi] >> (b0 + 4)) & 1u) ? FONE : 0u;
            }
            #pragma unroll
            for (int ni = 0; ni < 4; ni++) {
                int c0 = wx * 32 + ni * 8;
                bh[ni][0] = sB[(k0 + tq) * BP4 + c0 + gq];
                bh[ni][1] = sB[(k0 + tq + 4) * BP4 + c0 + gq];
                bl[ni][0] = sB[16 * BP4 + (k0 + tq) * BP4 + c0 + gq];
                bl[ni][1] = sB[16 * BP4 + (k0 + tq + 4) * BP4 + c0 + gq];
            }
            #pragma unroll
            for (int mi = 0; mi < 3; mi++)
                #pragma unroll
                for (int ni = 0; ni < 4; ni++) {
                    mma8(acc[mi][ni], af[mi], bh[ni]);
                    mma8(acc[mi][ni], af[mi], bl[ni]);
                }
        }
        __syncthreads();
    }
    #pragma unroll
    for (int mi = 0; mi < 3; mi++)
        #pragma unroll
        for (int ni = 0; ni < 4; ni++)
            #pragma unroll
            for (int e = 0; e < 4; e++) {
                int r = wy * 48 + mi * 16 + gq + (e >> 1) * 8;
                int c = wx * 32 + ni * 8 + 2 * tq + (e & 1);
                sE[r * SEP2 + c] = acc[mi][ni][e] * sdegE[r];
            }
    #pragma unroll
    for (int mi = 0; mi < 3; mi++)
        #pragma unroll
        for (int ni = 0; ni < 4; ni++)
            #pragma unroll
            for (int e = 0; e < 4; e++) acc[mi][ni][e] = 0.f;
    __syncthreads();

    // ---- hop 1: Y = (H^T @ E) / deg_v  (A bits from node-major sHT) ----
    for (int kc = 0; kc < 192; kc += 16) {
        float e0v = sE[(kc + kr) * SEP2 + c4];
        float e1v = sE[(kc + kr) * SEP2 + c4 + 1];
        float e2v = sE[(kc + kr) * SEP2 + c4 + 2];
        float e3v = sE[(kc + kr) * SEP2 + c4 + 3];
        hilo(e0v, sB[kr * BP4 + c4],     sB[16 * BP4 + kr * BP4 + c4]);
        hilo(e1v, sB[kr * BP4 + c4 + 1], sB[16 * BP4 + kr * BP4 + c4 + 1]);
        hilo(e2v, sB[kr * BP4 + c4 + 2], sB[16 * BP4 + kr * BP4 + c4 + 2]);
        hilo(e3v, sB[kr * BP4 + c4 + 3], sB[16 * BP4 + kr * BP4 + c4 + 3]);
        __syncthreads();
        int kw = kc >> 5, sh = kc & 31;
        unsigned ht0[3], ht1[3];
        #pragma unroll
        for (int mi = 0; mi < 3; mi++) {
            int nrow = wy * 48 + mi * 16 + gq;
            ht0[mi] = sHT[nrow * 6 + kw];
            ht1[mi] = sHT[(nrow + 8) * 6 + kw];
        }
        #pragma unroll
        for (int k0 = 0; k0 < 16; k0 += 8) {
            unsigned af[3][4], bh[4][2], bl[4][2];
            int b0 = sh + k0 + tq;
            #pragma unroll
            for (int mi = 0; mi < 3; mi++) {
                af[mi][0] = ((ht0[mi] >> b0) & 1u)       ? FONE : 0u;
                af[mi][1] = ((ht1[mi] >> b0) & 1u)       ? FONE : 0u;
                af[mi][2] = ((ht0[mi] >> (b0 + 4)) & 1u) ? FONE : 0u;
                af[mi][3] = ((ht1[mi] >> (b0 + 4)) & 1u) ? FONE : 0u;
            }
            #pragma unroll
            for (int ni = 0; ni < 4; ni++) {
                int c0 = wx * 32 + ni * 8;
                bh[ni][0] = sB[(k0 + tq) * BP4 + c0 + gq];
                bh[ni][1] = sB[(k0 + tq + 4) * BP4 + c0 + gq];
                bl[ni][0] = sB[16 * BP4 + (k0 + tq) * BP4 + c0 + gq];
                bl[ni][1] = sB[16 * BP4 + (k0 + tq + 4) * BP4 + c0 + gq];
            }
            #pragma unroll
            for (int mi = 0; mi < 3; mi++)
                #pragma unroll
                for (int ni = 0; ni < 4; ni++) {
                    mma8(acc[mi][ni], af[mi], bh[ni]);
                    mma8(acc[mi][ni], af[mi], bl[ni]);
                }
        }
        __syncthreads();
    }
    #pragma unroll
    for (int mi = 0; mi < 3; mi++)
        #pragma unroll
        for (int ni = 0; ni < 4; ni++)
            #pragma unroll
            for (int e = 0; e < 4; e++) {
                int r = wy * 48 + mi * 16 + gq + (e >> 1) * 8;
                int c = n0 + wx * 32 + ni * 8 + 2 * tq + (e & 1);
                g_Y[(size_t)(d * M + r) * G + c] = acc[mi][ni][e] * sdegV[r];
            }
}

// ---------------- K6: out = relu(Y @ W_h + b_h) (tf32 mma), regrouped ----------------
__global__ void __launch_bounds__(256) k_out_mma(const float* Wh, const float* bh,
                                                 float* out) {
    __shared__ unsigned sA[128 * FAP];
    __shared__ unsigned sB[32 * FBP];
    int bn = blockIdx.x, bm = blockIdx.y;
    int tid = threadIdx.x, lane = tid & 31, warp = tid >> 5;
    int wy = warp >> 1, wx = warp & 1;
    int gq = lane >> 2, tq = lane & 3;

    float acc[2][8][4];
    #pragma unroll
    for (int mi = 0; mi < 2; mi++)
        #pragma unroll
        for (int ni = 0; ni < 8; ni++)
            #pragma unroll
            for (int e = 0; e < 4; e++) acc[mi][ni][e] = 0.f;

    for (int kc = 0; kc < G; kc += 32) {
        #pragma unroll
        for (int it = 0; it < 4; it++) {
            int idx = tid + it * 256;
            int r = idx >> 3, c = (idx & 7) * 4;
            float4 xv = *(const float4*)(g_Y + (size_t)(bm * 128 + r) * G + kc + c);
            sA[r * FAP + c]     = f2tf(xv.x);
            sA[r * FAP + c + 1] = f2tf(xv.y);
            sA[r * FAP + c + 2] = f2tf(xv.z);
            sA[r * FAP + c + 3] = f2tf(xv.w);
        }
        #pragma unroll
        for (int it = 0; it < 4; it++) {
            int idx = tid + it * 256;
            int kr = idx >> 5, n4 = (idx & 31) * 4;
            float4 wv = *(const float4*)(Wh + (size_t)(kc + kr) * G + bn * 128 + n4);
            sB[kr * FBP + n4]     = f2tf(wv.x);
            sB[kr * FBP + n4 + 1] = f2tf(wv.y);
            sB[kr * FBP + n4 + 2] = f2tf(wv.z);
            sB[kr * FBP + n4 + 3] = f2tf(wv.w);
        }
        __syncthreads();
        #pragma unroll
        for (int k0 = 0; k0 < 32; k0 += 8) {
            unsigned af[2][4], bf[8][2];
            #pragma unroll
            for (int mi = 0; mi < 2; mi++) {
                int row = wy * 32 + mi * 16;
                af[mi][0] = sA[(row + gq) * FAP + k0 + tq];
                af[mi][1] = sA[(row + gq + 8) * FAP + k0 + tq];
                af[mi][2] = sA[(row + gq) * FAP + k0 + tq + 4];
                af[mi][3] = sA[(row + gq + 8) * FAP + k0 + tq + 4];
            }
            #pragma unroll
            for (int ni = 0; ni < 8; ni++) {
                int c0 = wx * 64 + ni * 8;
                bf[ni][0] = sB[(k0 + tq) * FBP + c0 + gq];
                bf[ni][1] = sB[(k0 + tq + 4) * FBP + c0 + gq];
            }
            #pragma unroll
            for (int mi = 0; mi < 2; mi++)
                #pragma unroll
                for (int ni = 0; ni < 8; ni++)
                    mma8(acc[mi][ni], af[mi], bf[ni]);
        }
        __syncthreads();
    }
    #pragma unroll
    for (int mi = 0; mi < 2; mi++)
        #pragma unroll
        for (int ni = 0; ni < 8; ni++)
            #pragma unroll
            for (int e = 0; e < 4; e++) {
                int gn = bm * 128 + wy * 32 + mi * 16 + gq + (e >> 1) * 8;
                int gc = bn * 128 + wx * 64 + ni * 8 + 2 * tq + (e & 1);
                int dd = gn / M, n = gn % M, mod = n >> 6, ii = n & 63;
                out[(size_t)(dd * L + ii) * 768 + mod * 256 + gc] =
                    fmaxf(acc[mi][ni][e] + bh[gc], 0.f);
            }
}

// ---------------- K7: norms, diag sims, zero LSE accumulators, bf16 convert ----------------
__global__ void k_norm(const float* out) {
    int i = blockIdx.x;
    int tid = threadIdx.x;
    float tv = out[(size_t)i * 768 + tid];
    float av = out[(size_t)i * 768 + 256 + tid];
    float vv = out[(size_t)i * 768 + 512 + tid];
    float q[6] = { tv * tv, av * av, vv * vv, tv * av, tv * vv, av * vv };
    __shared__ float red[6][8];
    __shared__ float sinv[3];
    int lane = tid & 31, w = tid >> 5;
    #pragma unroll
    for (int o = 16; o; o >>= 1)
        #pragma unroll
        for (int k = 0; k < 6; k++) q[k] += __shfl_down_sync(0xffffffffu, q[k], o);
    if (lane == 0)
        #pragma unroll
        for (int k = 0; k < 6; k++) red[k][w] = q[k];
    __syncthreads();
    if (tid == 0) {
        float s[6];
        #pragma unroll
        for (int k = 0; k < 6; k++) {
            s[k] = 0.f;
            #pragma unroll
            for (int w2 = 0; w2 < 8; w2++) s[k] += red[k][w2];
        }
        float it = 1.f / (sqrtf(s[0]) + 1e-8f);
        float ia = 1.f / (sqrtf(s[1]) + 1e-8f);
        float iv = 1.f / (sqrtf(s[2]) + 1e-8f);
        sinv[0] = it * SQTAUI; sinv[1] = ia * SQTAUI; sinv[2] = iv * SQTAUI;
        g_diag[i]             = s[3] * it * ia * TAUINV;
        g_diag[NROWS + i]     = s[4] * it * iv * TAUINV;
        g_diag[2 * NROWS + i] = s[5] * ia * iv * TAUINV;
        g_rowsum[i] = 0.f; g_rowsum[NROWS + i] = 0.f; g_rowsum[2 * NROWS + i] = 0.f;
        g_colsum[i] = 0.f; g_colsum[NROWS + i] = 0.f; g_colsum[2 * NROWS + i] = 0.f;
    }
    __syncthreads();
    g_nb[((size_t)0 * NROWS + i) * G + tid] = __float2bfloat16(tv * sinv[0]);
    g_nb[((size_t)1 * NROWS + i) * G + tid] = __float2bfloat16(av * sinv[1]);
    g_nb[((size_t)2 * NROWS + i) * G + tid] = __float2bfloat16(vv * sinv[2]);
}

// ---------------- K8: bf16 sim tiles; X panel resident, 4 col tiles per block ----------------
#define SPITCH 40
#define XPITCH 264
#define SIM_SMEM (128*XPITCH*2 + 2*128*SPITCH*2 + 256*4)
__global__ void __launch_bounds__(256) k_sim_mma() {
    extern __shared__ __align__(16) char dsm[];
    __nv_bfloat16* sXp = (__nv_bfloat16*)dsm;                       // 128 x 256 panel
    __nv_bfloat16* sY  = sXp + 128 * XPITCH;                         // 2 x 128 x SPITCH
    float* srow = (float*)(sY + 2 * 128 * SPITCH);
    float* scol = srow + 128;

    int p = blockIdx.z;
    int mx = (p == 2) ? 1 : 0;
    int my = (p == 0) ? 1 : 2;
    int row0 = blockIdx.y * 128;
    int tid = threadIdx.x, lane = tid & 31, warp = tid >> 5;
    int wy = warp >> 1, wx = warp & 1;      // warp tile: 32 rows x 64 cols

    const __nv_bfloat16* xg = g_nb + ((size_t)mx * NROWS + row0) * G;

    #pragma unroll
    for (int it = 0; it < 16; it++) {
        int idx = tid + it * 256;
        int r = idx >> 5, c = (idx & 31) * 8;
        cp16(sXp + r * XPITCH + c, xg + (size_t)r * G + c);
    }
    cp_commit();
    asm volatile("cp.async.wait_group 0;");
    __syncthreads();

    int lr = tid >> 2, lc = (tid & 3) * 8;
    int lr2 = lr + 64;

    for (int j = 0; j < 4; j++) {
        int col0 = (blockIdx.x * 4 + j) * 128;
        const __nv_bfloat16* yg = g_nb + ((size_t)my * NROWS + col0) * G;

        float acc[2][8][4];
        #pragma unroll
        for (int mi = 0; mi < 2; mi++)
            #pragma unroll
            for (int ni = 0; ni < 8; ni++)
                #pragma unroll
                for (int r = 0; r < 4; r++) acc[mi][ni][r] = 0.f;

        cp16(sY + lr * SPITCH + lc,  yg + (size_t)lr * G + lc);
        cp16(sY + lr2 * SPITCH + lc, yg + (size_t)lr2 * G + lc);
        cp_commit();

        #pragma unroll
        for (int c = 0; c < 8; c++) {
            int cur = c & 1;
            if (c < 7) {
                int nb = (c + 1) & 1, kc2 = (c + 1) * 32;
                cp16(sY + nb * 128 * SPITCH + lr * SPITCH + lc,
                     yg + (size_t)lr * G + kc2 + lc);
                cp16(sY + nb * 128 * SPITCH + lr2 * SPITCH + lc,
                     yg + (size_t)lr2 * G + kc2 + lc);
                cp_commit();
                asm volatile("cp.async.wait_group 1;");
            } else {
                asm volatile("cp.async.wait_group 0;");
            }
            __syncthreads();
            int kc = c * 32;
            #pragma unroll
            for (int ks = 0; ks < 2; ks++) {
                int k0 = ks * 16;
                unsigned A[2][4];
                #pragma unroll
                for (int mi = 0; mi < 2; mi++) {
                    int r = wy * 32 + mi * 16 + ((lane >> 3) & 1) * 8 + (lane & 7);
                    int cc = kc + k0 + (lane >> 4) * 8;
                    unsigned ad = (unsigned)__cvta_generic_to_shared(sXp + r * XPITCH + cc);
                    asm volatile("ldmatrix.sync.aligned.m8n8.x4.shared.b16 {%0,%1,%2,%3},[%4];"
                        : "=r"(A[mi][0]), "=r"(A[mi][1]), "=r"(A[mi][2]), "=r"(A[mi][3])
                        : "r"(ad));
                }
                unsigned B[8][2];
                #pragma unroll
                for (int nb2 = 0; nb2 < 4; nb2++) {
                    int r = wx * 64 + nb2 * 16 + (lane >> 4) * 8 + (lane & 7);
                    int cc = k0 + ((lane >> 3) & 1) * 8;
                    unsigned ad = (unsigned)__cvta_generic_to_shared(
                        sY + cur * 128 * SPITCH + r * SPITCH + cc);
                    asm volatile("ldmatrix.sync.aligned.m8n8.x4.shared.b16 {%0,%1,%2,%3},[%4];"
                        : "=r"(B[2 * nb2][0]), "=r"(B[2 * nb2][1]),
                          "=r"(B[2 * nb2 + 1][0]), "=r"(B[2 * nb2 + 1][1])
                        : "r"(ad));
                }
                #pragma unroll
                for (int mi = 0; mi < 2; mi++)
                    #pragma unroll
                    for (int ni = 0; ni < 8; ni++)
                        asm volatile(
                            "mma.sync.aligned.m16n8k16.row.col.f32.bf16.bf16.f32 "
                            "{%0,%1,%2,%3},{%4,%5,%6,%7},{%8,%9},{%0,%1,%2,%3};"
                            : "+f"(acc[mi][ni][0]), "+f"(acc[mi][ni][1]),
                              "+f"(acc[mi][ni][2]), "+f"(acc[mi][ni][3])
                            : "r"(A[mi][0]), "r"(A[mi][1]), "r"(A[mi][2]), "r"(A[mi][3]),
                              "r"(B[ni][0]), "r"(B[ni][1]));
            }
            __syncthreads();
        }

        if (tid < 128) { srow[tid] = 0.f; scol[tid] = 0.f; }
        __syncthreads();

        float rowp[2][2] = {{0.f, 0.f}, {0.f, 0.f}};
        float colp[8][2];
        #pragma unroll
        for (int ni = 0; ni < 8; ni++) { colp[ni][0] = 0.f; colp[ni][1] = 0.f; }
        #pragma unroll
        for (int mi = 0; mi < 2; mi++)
            #pragma unroll
            for (int ni = 0; ni < 8; ni++)
                #pragma unroll
                for (int r = 0; r < 4; r++) {
                    float e = __expf(acc[mi][ni][r]);
                    rowp[mi][r >> 1] += e;
                    colp[ni][r & 1] += e;
                }

        #pragma unroll
        for (int mi = 0; mi < 2; mi++)
            #pragma unroll
            for (int h = 0; h < 2; h++) {
                float vv = rowp[mi][h];
                vv += __shfl_xor_sync(0xffffffffu, vv, 1);
                vv += __shfl_xor_sync(0xffffffffu, vv, 2);
                if ((lane & 3) == 0)
                    atomicAdd(&srow[wy * 32 + mi * 16 + (lane >> 2) + h * 8], vv);
            }
        #pragma unroll
        for (int ni = 0; ni < 8; ni++)
            #pragma unroll
            for (int s2 = 0; s2 < 2; s2++) {
                float vv = colp[ni][s2];
                vv += __shfl_xor_sync(0xffffffffu, vv, 4);
                vv += __shfl_xor_sync(0xffffffffu, vv, 8);
                vv += __shfl_xor_sync(0xffffffffu, vv, 16);
                if (lane < 4)
                    atomicAdd(&scol[wx * 64 + ni * 8 + lane * 2 + s2], vv);
            }
        __syncthreads();
        if (tid < 128) {
            atomicAdd(&g_rowsum[p * NROWS + row0 + tid], srow[tid]);
            atomicAdd(&g_colsum[p * NROWS + col0 + tid], scol[tid]);
        }
        __syncthreads();
    }
}

// ---------------- K9: final loss reduction ----------------
__global__ void k_loss(float* out, int out_size) {
    int tid = threadIdx.x;
    float s = 0.f;
    for (int idx = tid; idx < 3 * NROWS; idx += 256) {
        float dg = g_diag[idx];
        s += 2.f * dg - logf(g_rowsum[idx]) - logf(g_colsum[idx]);
    }
    __shared__ float red[8];
    int lane = tid & 31, w = tid >> 5;
    #pragma unroll
    for (int o = 16; o; o >>= 1) s += __shfl_down_sync(0xffffffffu, s, o);
    if (lane == 0) red[w] = s;
    __syncthreads();
    if (tid == 0) {
        float tot = 0.f;
        #pragma unroll
        for (int w2 = 0; w2 < 8; w2++) tot += red[w2];
        float loss = -tot / (2.f * 3.f * (float)NROWS);
        if (out_size > NROWS * 768) out[NROWS * 768] = loss;
    }
}

// ---------------- launcher ----------------
extern "C" void kernel_launch(void* const* d_in, const int* in_sizes, int n_in,
                              void* d_out, int out_size) {
    const float* t   = (const float*)d_in[0];
    const float* a   = (const float*)d_in[1];
    const float* v   = (const float*)d_in[2];
    const float* Wfc = (const float*)d_in[3];
    const float* bfc = (const float*)d_in[4];
    const float* Wh  = (const float*)d_in[5];
    const float* bh  = (const float*)d_in[6];
    float* out = (float*)d_out;

    cudaFuncSetAttribute(k_sim_mma,
        cudaFuncAttributeMaxDynamicSharedMemorySize, SIM_SMEM);
    cudaFuncSetAttribute(k_agg_f,
        cudaFuncAttributeMaxDynamicSharedMemorySize, AGG_SMEM);
    cudaFuncSetAttribute(k_gram_mma,
        cudaFuncAttributeMaxDynamicSharedMemorySize, GRAM_SMEM);

    k_sq<<<NNODE / 8, 256>>>(t, a, v);
    k_gram_mma<<<dim3(6, 64), 256, GRAM_SMEM>>>();
    k_fc_mma<<<dim3(2, 96), 256>>>(Wfc, bfc);
    k_agg_f<<<dim3(4, 64), 256, AGG_SMEM>>>();
    k_out_mma<<<dim3(2, 96), 256>>>(Wh, bh, out);
    k_norm<<<NROWS, 256>>>(out);
    k_sim_mma<<<dim3(8, 32, 3), 256, SIM_SMEM>>>();
    k_loss<<<1, 256>>>(out, out_size);
}

// round 17
// speedup vs baseline: 1.1538x; 1.0017x over previous
#include <cuda_runtime.h>
#include <cuda_bf16.h>
#include <math.h>
#include <float.h>

#define D 64
#define L 64
#define DIMF 512
#define G 256
#define M 192                 // 3*L nodes (= hyperedges) per dialogue
#define KTOP 12
#define NROWS 4096            // D*L
#define NNODE (D*M)           // 12288
#define TAUINV (1.0f/0.07f)
#define SQTAUI 3.7796447300922722f   // sqrt(1/0.07)

// ---- scratch (static device arrays; no allocation allowed) ----
__device__ float    g_sq[NNODE];
__device__ unsigned g_fh[(size_t)NNODE*DIMF];   // tf32 hi of features
__device__ unsigned g_fl[(size_t)NNODE*DIMF];   // tf32 lo of features
__device__ unsigned g_H[NNODE*6];       // 192-bit incidence mask per edge
__device__ float    g_X[NNODE*G];
__device__ float    g_Y[NNODE*G];
__device__ float    g_diag[3*NROWS];
__device__ float    g_rowsum[3*NROWS];
__device__ float    g_colsum[3*NROWS];
__device__ __nv_bfloat16 g_nb[(size_t)3*NROWS*G];   // normalized bf16 features (loss path only)

__device__ __forceinline__ const float* feat_row(int d, int n,
        const float* t, const float* a, const float* v) {
    int mod = n >> 6, i = n & 63;
    const float* base = (mod == 0) ? t : (mod == 1) ? a : v;
    return base + (size_t)(d * L + i) * DIMF;
}

// ---- tf32 helpers ----
__device__ __forceinline__ unsigned f2tf(float x) {
    unsigned u; asm("cvt.rna.tf32.f32 %0, %1;" : "=r"(u) : "f"(x)); return u;
}
__device__ __forceinline__ void hilo(float x, unsigned& h, unsigned& l) {
    h = f2tf(x);
    l = f2tf(x - __uint_as_float(h));
}
__device__ __forceinline__ void mma8(float* c, const unsigned* a, const unsigned* b) {
    asm volatile("mma.sync.aligned.m16n8k8.row.col.f32.tf32.tf32.f32 "
        "{%0,%1,%2,%3},{%4,%5,%6,%7},{%8,%9},{%0,%1,%2,%3};"
        : "+f"(c[0]), "+f"(c[1]), "+f"(c[2]), "+f"(c[3])
        : "r"(a[0]), "r"(a[1]), "r"(a[2]), "r"(a[3]), "r"(b[0]), "r"(b[1]));
}

// ---- cp.async helpers ----
__device__ __forceinline__ void cp16(void* dst_smem, const void* src) {
    unsigned ad = (unsigned)__cvta_generic_to_shared(dst_smem);
    asm volatile("cp.async.cg.shared.global [%0],[%1],16;" :: "r"(ad), "l"(src));
}
__device__ __forceinline__ void cp_commit() {
    asm volatile("cp.async.commit_group;");
}

// ---------------- K1: per-node squared norms + hi/lo precompute ----------------
__global__ void k_sq(const float* t, const float* a, const float* v) {
    int warp = (blockIdx.x * blockDim.x + threadIdx.x) >> 5;
    int lane = threadIdx.x & 31;
    if (warp >= NNODE) return;
    int d = warp / M, n = warp % M;
    const float* r = feat_row(d, n, t, a, v);
    float s = 0.f;
    #pragma unroll
    for (int c = lane; c < DIMF; c += 32) { float x = r[c]; s += x * x; }
    unsigned* fh = g_fh + (size_t)warp * DIMF;
    unsigned* fl = g_fl + (size_t)warp * DIMF;
    #pragma unroll
    for (int c0 = lane * 4; c0 < DIMF; c0 += 128) {
        float4 x = *(const float4*)(r + c0);
        uint4 h, l;
        hilo(x.x, h.x, l.x); hilo(x.y, h.y, l.y);
        hilo(x.z, h.z, l.z); hilo(x.w, h.w, l.w);
        *(uint4*)(fh + c0) = h;
        *(uint4*)(fl + c0) = l;
    }
    #pragma unroll
    for (int o = 16; o; o >>= 1) s += __shfl_down_sync(0xffffffffu, s, o);
    if (lane == 0) g_sq[warp] = s;
}

// ---------------- K2: 3xTF32 gram, double-buffered cp.async pipeline ----------------
#define GBP2 20
#define GRAM_SMEM (2 * 2 * 192 * GBP2 * 4 + M * 4)
__global__ void __launch_bounds__(256) k_gram_mma() {
    extern __shared__ __align__(16) char gsm[];
    unsigned* Bbuf0 = (unsigned*)gsm;
    unsigned* Bbuf1 = Bbuf0 + 2 * 192 * GBP2;
    float* sq = (float*)(Bbuf1 + 2 * 192 * GBP2);

    int d = blockIdx.y, i0 = blockIdx.x * 32;
    int tid = threadIdx.x, lane = tid & 31, warp = tid >> 5;
    int gq = lane >> 2, tq = lane & 3;
    if (tid < M) sq[tid] = g_sq[d * M + tid];
    size_t base = (size_t)(d * M) * DIMF;

    int ln[3], lk[3];
    #pragma unroll
    for (int it = 0; it < 3; it++) {
        int idx = tid + it * 256;
        ln[it] = idx >> 2; lk[it] = (idx & 3) * 4;
    }

    float acc[2][3][4];
    #pragma unroll
    for (int mi = 0; mi < 2; mi++)
        #pragma unroll
        for (int ni = 0; ni < 3; ni++)
            #pragma unroll
            for (int e = 0; e < 4; e++) acc[mi][ni][e] = 0.f;

    #pragma unroll
    for (int it = 0; it < 3; it++) {
        cp16(Bbuf0 + ln[it] * GBP2 + lk[it],
             g_fh + base + (size_t)ln[it] * DIMF + lk[it]);
        cp16(Bbuf0 + 192 * GBP2 + ln[it] * GBP2 + lk[it],
             g_fl + base + (size_t)ln[it] * DIMF + lk[it]);
    }
    cp_commit();

    for (int c = 0; c < 32; c++) {
        if (c < 31) {
            unsigned* nb = (c & 1) ? Bbuf0 : Bbuf1;
            int kc2 = (c + 1) * 16;
            #pragma unroll
            for (int it = 0; it < 3; it++) {
                cp16(nb + ln[it] * GBP2 + lk[it],
                     g_fh + base + (size_t)ln[it] * DIMF + kc2 + lk[it]);
                cp16(nb + 192 * GBP2 + ln[it] * GBP2 + lk[it],
                     g_fl + base + (size_t)ln[it] * DIMF + kc2 + lk[it]);
            }
            cp_commit();
            asm volatile("cp.async.wait_group 1;");
        } else {
            asm volatile("cp.async.wait_group 0;");
        }
        __syncthreads();
        unsigned* Bhi = (c & 1) ? Bbuf1 : Bbuf0;
        unsigned* Blo = Bhi + 192 * GBP2;
        #pragma unroll
        for (int k0 = 0; k0 < 16; k0 += 8) {
            unsigned ah[2][4], al[2][4], bh[3][2], bl[3][2];
            #pragma unroll
            for (int mi = 0; mi < 2; mi++) {
                int r0 = (i0 + mi * 16 + gq) * GBP2;
                int r1 = r0 + 8 * GBP2;
                ah[mi][0] = Bhi[r0 + k0 + tq];
                ah[mi][1] = Bhi[r1 + k0 + tq];
                ah[mi][2] = Bhi[r0 + k0 + tq + 4];
                ah[mi][3] = Bhi[r1 + k0 + tq + 4];
                al[mi][0] = Blo[r0 + k0 + tq];
                al[mi][1] = Blo[r1 + k0 + tq];
                al[mi][2] = Blo[r0 + k0 + tq + 4];
                al[mi][3] = Blo[r1 + k0 + tq + 4];
            }
            #pragma unroll
            for (int ni = 0; ni < 3; ni++) {
                int c0 = (warp * 24 + ni * 8 + gq) * GBP2;
                bh[ni][0] = Bhi[c0 + k0 + tq];
                bh[ni][1] = Bhi[c0 + k0 + tq + 4];
                bl[ni][0] = Blo[c0 + k0 + tq];
                bl[ni][1] = Blo[c0 + k0 + tq + 4];
            }
            #pragma unroll
            for (int mi = 0; mi < 2; mi++)
                #pragma unroll
                for (int ni = 0; ni < 3; ni++) {
                    mma8(acc[mi][ni], ah[mi], bh[ni]);
                    mma8(acc[mi][ni], ah[mi], bl[ni]);
                    mma8(acc[mi][ni], al[mi], bh[ni]);
                }
        }
        __syncthreads();
    }

    float* d2s = (float*)Bbuf0;
    #pragma unroll
    for (int mi = 0; mi < 2; mi++)
        #pragma unroll
        for (int ni = 0; ni < 3; ni++)
            #pragma unroll
            for (int e = 0; e < 4; e++) {
                int r = mi * 16 + gq + (e >> 1) * 8;
                int c = warp * 24 + ni * 8 + 2 * tq + (e & 1);
                float v2 = sq[i0 + r] + sq[c] - 2.f * acc[mi][ni][e];
                d2s[r * 192 + c] = fmaxf(v2, 0.f);
            }
    __syncthreads();

    int tx = lane;
    for (int q = 0; q < 4; q++) {
        int r = warp * 4 + q;
        float val[6];
        #pragma unroll
        for (int s = 0; s < 6; s++) val[s] = d2s[r * 192 + tx + 32 * s];
        unsigned mask[6] = {0, 0, 0, 0, 0, 0};
        for (int pick = 0; pick < KTOP; pick++) {
            float bv = val[0]; int bi = tx;
            #pragma unroll
            for (int s = 1; s < 6; s++) {
                float vv = val[s];
                if (vv < bv) { bv = vv; bi = tx + 32 * s; }
            }
            #pragma unroll
            for (int o = 16; o; o >>= 1) {
                float ov = __shfl_down_sync(0xffffffffu, bv, o);
                int   oi = __shfl_down_sync(0xffffffffu, bi, o);
                if (ov < bv || (ov == bv && oi < bi)) { bv = ov; bi = oi; }
            }
            bi = __shfl_sync(0xffffffffu, bi, 0);
            if ((bi & 31) == tx) val[bi >> 5] = FLT_MAX;
            mask[bi >> 5] |= 1u << (bi & 31);
        }
        if (tx == 0) {
            int e = i0 + r;
            int u = e / 3;
            mask[u >> 5]           |= 1u << (u & 31);
            mask[(u + 64) >> 5]    |= 1u << ((u + 64) & 31);
            mask[(u + 128) >> 5]   |= 1u << ((u + 128) & 31);
            #pragma unroll
            for (int w = 0; w < 6; w++)
                g_H[(size_t)(d * M + e) * 6 + w] = mask[w];
        }
    }
}

// ---------------- K3: X = feat @ W_fc + b_fc  (tf32 mma, 128x128 tile) ----------------
#define FAP 36
#define FBP 136
__global__ void __launch_bounds__(256) k_fc_mma(const float* Wfc, const float* bfc) {
    __shared__ unsigned sA[128 * FAP];
    __shared__ unsigned sB[32 * FBP];
    int bn = blockIdx.x, bm = blockIdx.y;
    int tid = threadIdx.x, lane = tid & 31, warp = tid >> 5;
    int wy = warp >> 1, wx = warp & 1;
    int gq = lane >> 2, tq = lane & 3;

    float acc[2][8][4];
    #pragma unroll
    for (int mi = 0; mi < 2; mi++)
        #pragma unroll
        for (int ni = 0; ni < 8; ni++)
            #pragma unroll
            for (int e = 0; e < 4; e++) acc[mi][ni][e] = 0.f;

    for (int kc = 0; kc < DIMF; kc += 32) {
        #pragma unroll
        for (int it = 0; it < 4; it++) {
            int idx = tid + it * 256;
            int r = idx >> 3, c = (idx & 7) * 4;
            cp16(sA + r * FAP + c, g_fh + (size_t)(bm * 128 + r) * DIMF + kc + c);
        }
        cp_commit();
        #pragma unroll
        for (int it = 0; it < 4; it++) {
            int idx = tid + it * 256;
            int kr = idx >> 5, n4 = (idx & 31) * 4;
            float4 wv = *(const float4*)(Wfc + (size_t)(kc + kr) * G + bn * 128 + n4);
            sB[kr * FBP + n4]     = f2tf(wv.x);
            sB[kr * FBP + n4 + 1] = f2tf(wv.y);
            sB[kr * FBP + n4 + 2] = f2tf(wv.z);
            sB[kr * FBP + n4 + 3] = f2tf(wv.w);
        }
        asm volatile("cp.async.wait_group 0;");
        __syncthreads();
        #pragma unroll
        for (int k0 = 0; k0 < 32; k0 += 8) {
            unsigned af[2][4], bf[8][2];
            #pragma unroll
            for (int mi = 0; mi < 2; mi++) {
                int row = wy * 32 + mi * 16;
                af[mi][0] = sA[(row + gq) * FAP + k0 + tq];
                af[mi][1] = sA[(row + gq + 8) * FAP + k0 + tq];
                af[mi][2] = sA[(row + gq) * FAP + k0 + tq + 4];
                af[mi][3] = sA[(row + gq + 8) * FAP + k0 + tq + 4];
            }
            #pragma unroll
            for (int ni = 0; ni < 8; ni++) {
                int c0 = wx * 64 + ni * 8;
                bf[ni][0] = sB[(k0 + tq) * FBP + c0 + gq];
                bf[ni][1] = sB[(k0 + tq + 4) * FBP + c0 + gq];
            }
            #pragma unroll
            for (int mi = 0; mi < 2; mi++)
                #pragma unroll
                for (int ni = 0; ni < 8; ni++)
                    mma8(acc[mi][ni], af[mi], bf[ni]);
        }
        __syncthreads();
    }
    #pragma unroll
    for (int mi = 0; mi < 2; mi++)
        #pragma unroll
        for (int ni = 0; ni < 8; ni++)
            #pragma unroll
            for (int e = 0; e < 4; e++) {
                int r  = bm * 128 + wy * 32 + mi * 16 + gq + (e >> 1) * 8;
                int cc = bn * 128 + wx * 64 + ni * 8 + 2 * tq + (e & 1);
                g_X[(size_t)r * G + cc] = acc[mi][ni][e] + bfc[cc];
            }
}

// ---------------- K4: fused hypergraph hops, 64-col blocks ----------------
#define BP4 72     // B pitch (64 + 8)
#define SEP2 66    // E tile pitch (64 + 2)
#define FONE 0x3F800000u
#define AGG_SMEM ((192*6 + 192*6 + 2*16*BP4)*4 + (192 + 192 + 192*SEP2)*4)
__global__ void __launch_bounds__(256) k_agg_f() {
    extern __shared__ __align__(16) char asm_[];
    unsigned* sHw  = (unsigned*)asm_;
    unsigned* sHT  = sHw + 192 * 6;
    unsigned* sB   = sHT + 192 * 6;
    float*    sdegE = (float*)(sB + 2 * 16 * BP4);
    float*    sdegV = sdegE + 192;
    float*    sE   = sdegV + 192;
    int d = blockIdx.y, n0 = blockIdx.x * 64;
    int tid = threadIdx.x, lane = tid & 31, warp = tid >> 5;
    int wy = warp >> 1, wx = warp & 1;
    int gq = lane >> 2, tq = lane & 3;

    for (int i = tid; i < 192 * 6; i += 256) sHw[i] = g_H[(size_t)(d * M) * 6 + i];
    __syncthreads();

    for (int blk = warp; blk < 36; blk += 8) {
        int eb = blk / 6, nb = blk % 6;
        unsigned x = sHw[(eb * 32 + lane) * 6 + nb];
        #pragma unroll
        for (int i = 16; i >= 1; i >>= 1) {
            unsigned m = 0xFFFFFFFFu / ((1u << i) + 1u);
            unsigned y = __shfl_xor_sync(0xffffffffu, x, i);
            x = (lane & i) ? (((y >> i) & m) | (x & ~m))
                           : ((x & m) | ((y & m) << i));
        }
        sHT[(nb * 32 + lane) * 6 + eb] = x;
    }
    __syncthreads();

    if (tid < 192) {
        int dege = 0, degv = 0;
        #pragma unroll
        for (int w = 0; w < 6; w++) {
            dege += __popc(sHw[tid * 6 + w]);
            degv += __popc(sHT[tid * 6 + w]);
        }
        sdegE[tid] = 1.f / (float)dege;
        sdegV[tid] = 1.f / (float)degv;
    }

    float acc[3][4][4];
    #pragma unroll
    for (int mi = 0; mi < 3; mi++)
        #pragma unroll
        for (int ni = 0; ni < 4; ni++)
            #pragma unroll
            for (int e = 0; e < 4; e++) acc[mi][ni][e] = 0.f;

    int kr = tid >> 4, c4 = (tid & 15) * 4;
    float4 nxt = *(const float4*)(g_X + (size_t)(d * M + kr) * G + n0 + c4);

    // ---- hop 0: E = (H @ X) / deg_e ----
    for (int kc = 0; kc < 192; kc += 16) {
        hilo(nxt.x, sB[kr * BP4 + c4],     sB[16 * BP4 + kr * BP4 + c4]);
        hilo(nxt.y, sB[kr * BP4 + c4 + 1], sB[16 * BP4 + kr * BP4 + c4 + 1]);
        hilo(nxt.z, sB[kr * BP4 + c4 + 2], sB[16 * BP4 + kr * BP4 + c4 + 2]);
        hilo(nxt.w, sB[kr * BP4 + c4 + 3], sB[16 * BP4 + kr * BP4 + c4 + 3]);
        __syncthreads();
        if (kc + 16 < 192)
            nxt = *(const float4*)(g_X + (size_t)(d * M + kc + 16 + kr) * G + n0 + c4);
        int kw = kc >> 5, sh = kc & 31;
        unsigned hw0[3], hw1[3];
        #pragma unroll
        for (int mi = 0; mi < 3; mi++) {
            int e0 = wy * 48 + mi * 16 + gq;
            hw0[mi] = sHw[e0 * 6 + kw];
            hw1[mi] = sHw[(e0 + 8) * 6 + kw];
        }
        #pragma unroll
        for (int k0 = 0; k0 < 16; k0 += 8) {
            unsigned af[3][4], bh[4][2], bl[4][2];
            int b0 = sh + k0 + tq;
            #pragma unroll
            for (int mi = 0; mi < 3; mi++) {
                af[mi][0] = ((hw0[mi] >> b0) & 1u)       ? FONE : 0u;
                af[mi][1] = ((hw1[mi] >> b0) & 1u)       ? FONE : 0u;
                af[mi][2] = ((hw0[mi] >> (b0 + 4)) & 1u) ? FONE : 0u;
                af[mi][3] = ((hw1[mi] >> (b0 + 4)) & 1u) ? FONE : 0u;
            }
            #pragma unroll
            for (int ni = 0; ni < 4; ni++) {
                int c0 = wx * 32 + ni * 8;
                bh[ni][0] = sB[(k0 + tq) * BP4 + c0 + gq];
                bh[ni][1] = sB[(k0 + tq + 4) * BP4 + c0 + gq];
                bl[ni][0] = sB[16 * BP4 + (k0 + tq) * BP4 + c0 + gq];
                bl[ni][1] = sB[16 * BP4 + (k0 + tq + 4) * BP4 + c0 + gq];
            }
            #pragma unroll
            for (int mi = 0; mi < 3; mi++)
                #pragma unroll
                for (int ni = 0; ni < 4; ni++) {
                    mma8(acc[mi][ni], af[mi], bh[ni]);
                    mma8(acc[mi][ni], af[mi], bl[ni]);
                }
        }
        __syncthreads();
    }
    #pragma unroll
    for (int mi = 0; mi < 3; mi++)
        #pragma unroll
        for (int ni = 0; ni < 4; ni++)
            #pragma unroll
            for (int e = 0; e < 4; e++) {
                int r = wy * 48 + mi * 16 + gq + (e >> 1) * 8;
                int c = wx * 32 + ni * 8 + 2 * tq + (e & 1);
                sE[r * SEP2 + c] = acc[mi][ni][e] * sdegE[r];
            }
    #pragma unroll
    for (int mi = 0; mi < 3; mi++)
        #pragma unroll
        for (int ni = 0; ni < 4; ni++)
            #pragma unroll
            for (int e = 0; e < 4; e++) acc[mi][ni][e] = 0.f;
    __syncthreads();

    // ---- hop 1: Y = (H^T @ E) / deg_v ----
    for (int kc = 0; kc < 192; kc += 16) {
        float e0v = sE[(kc + kr) * SEP2 + c4];
        float e1v = sE[(kc + kr) * SEP2 + c4 + 1];
        float e2v = sE[(kc + kr) * SEP2 + c4 + 2];
        float e3v = sE[(kc + kr) * SEP2 + c4 + 3];
        hilo(e0v, sB[kr * BP4 + c4],     sB[16 * BP4 + kr * BP4 + c4]);
        hilo(e1v, sB[kr * BP4 + c4 + 1], sB[16 * BP4 + kr * BP4 + c4 + 1]);
        hilo(e2v, sB[kr * BP4 + c4 + 2], sB[16 * BP4 + kr * BP4 + c4 + 2]);
        hilo(e3v, sB[kr * BP4 + c4 + 3], sB[16 * BP4 + kr * BP4 + c4 + 3]);
        __syncthreads();
        int kw = kc >> 5, sh = kc & 31;
        unsigned ht0[3], ht1[3];
        #pragma unroll
        for (int mi = 0; mi < 3; mi++) {
            int nrow = wy * 48 + mi * 16 + gq;
            ht0[mi] = sHT[nrow * 6 + kw];
            ht1[mi] = sHT[(nrow + 8) * 6 + kw];
        }
        #pragma unroll
        for (int k0 = 0; k0 < 16; k0 += 8) {
            unsigned af[3][4], bh[4][2], bl[4][2];
            int b0 = sh + k0 + tq;
            #pragma unroll
            for (int mi = 0; mi < 3; mi++) {
                af[mi][0] = ((ht0[mi] >> b0) & 1u)       ? FONE : 0u;
                af[mi][1] = ((ht1[mi] >> b0) & 1u)       ? FONE : 0u;
                af[mi][2] = ((ht0[mi] >> (b0 + 4)) & 1u) ? FONE : 0u;
                af[mi][3] = ((ht1[mi] >> (b0 + 4)) & 1u) ? FONE : 0u;
            }
            #pragma unroll
            for (int ni = 0; ni < 4; ni++) {
                int c0 = wx * 32 + ni * 8;
                bh[ni][0] = sB[(k0 + tq) * BP4 + c0 + gq];
                bh[ni][1] = sB[(k0 + tq + 4) * BP4 + c0 + gq];
                bl[ni][0] = sB[16 * BP4 + (k0 + tq) * BP4 + c0 + gq];
                bl[ni][1] = sB[16 * BP4 + (k0 + tq + 4) * BP4 + c0 + gq];
            }
            #pragma unroll
            for (int mi = 0; mi < 3; mi++)
                #pragma unroll
                for (int ni = 0; ni < 4; ni++) {
                    mma8(acc[mi][ni], af[mi], bh[ni]);
                    mma8(acc[mi][ni], af[mi], bl[ni]);
                }
        }
        __syncthreads();
    }
    #pragma unroll
    for (int mi = 0; mi < 3; mi++)
        #pragma unroll
        for (int ni = 0; ni < 4; ni++)
            #pragma unroll
            for (int e = 0; e < 4; e++) {
                int r = wy * 48 + mi * 16 + gq + (e >> 1) * 8;
                int c = n0 + wx * 32 + ni * 8 + 2 * tq + (e & 1);
                g_Y[(size_t)(d * M + r) * G + c] = acc[mi][ni][e] * sdegV[r];
            }
}

// ---------------- K6: out = relu(Y @ W_h + b_h) (tf32 mma), regrouped ----------------
__global__ void __launch_bounds__(256) k_out_mma(const float* Wh, const float* bh,
                                                 float* out) {
    __shared__ unsigned sA[128 * FAP];
    __shared__ unsigned sB[32 * FBP];
    int bn = blockIdx.x, bm = blockIdx.y;
    int tid = threadIdx.x, lane = tid & 31, warp = tid >> 5;
    int wy = warp >> 1, wx = warp & 1;
    int gq = lane >> 2, tq = lane & 3;

    float acc[2][8][4];
    #pragma unroll
    for (int mi = 0; mi < 2; mi++)
        #pragma unroll
        for (int ni = 0; ni < 8; ni++)
            #pragma unroll
            for (int e = 0; e < 4; e++) acc[mi][ni][e] = 0.f;

    for (int kc = 0; kc < G; kc += 32) {
        #pragma unroll
        for (int it = 0; it < 4; it++) {
            int idx = tid + it * 256;
            int r = idx >> 3, c = (idx & 7) * 4;
            float4 xv = *(const float4*)(g_Y + (size_t)(bm * 128 + r) * G + kc + c);
            sA[r * FAP + c]     = f2tf(xv.x);
            sA[r * FAP + c + 1] = f2tf(xv.y);
            sA[r * FAP + c + 2] = f2tf(xv.z);
            sA[r * FAP + c + 3] = f2tf(xv.w);
        }
        #pragma unroll
        for (int it = 0; it < 4; it++) {
            int idx = tid + it * 256;
            int kr = idx >> 5, n4 = (idx & 31) * 4;
            float4 wv = *(const float4*)(Wh + (size_t)(kc + kr) * G + bn * 128 + n4);
            sB[kr * FBP + n4]     = f2tf(wv.x);
            sB[kr * FBP + n4 + 1] = f2tf(wv.y);
            sB[kr * FBP + n4 + 2] = f2tf(wv.z);
            sB[kr * FBP + n4 + 3] = f2tf(wv.w);
        }
        __syncthreads();
        #pragma unroll
        for (int k0 = 0; k0 < 32; k0 += 8) {
            unsigned af[2][4], bf[8][2];
            #pragma unroll
            for (int mi = 0; mi < 2; mi++) {
                int row = wy * 32 + mi * 16;
                af[mi][0] = sA[(row + gq) * FAP + k0 + tq];
                af[mi][1] = sA[(row + gq + 8) * FAP + k0 + tq];
                af[mi][2] = sA[(row + gq) * FAP + k0 + tq + 4];
                af[mi][3] = sA[(row + gq + 8) * FAP + k0 + tq + 4];
            }
            #pragma unroll
            for (int ni = 0; ni < 8; ni++) {
                int c0 = wx * 64 + ni * 8;
                bf[ni][0] = sB[(k0 + tq) * FBP + c0 + gq];
                bf[ni][1] = sB[(k0 + tq + 4) * FBP + c0 + gq];
            }
            #pragma unroll
            for (int mi = 0; mi < 2; mi++)
                #pragma unroll
                for (int ni = 0; ni < 8; ni++)
                    mma8(acc[mi][ni], af[mi], bf[ni]);
        }
        __syncthreads();
    }
    #pragma unroll
    for (int mi = 0; mi < 2; mi++)
        #pragma unroll
        for (int ni = 0; ni < 8; ni++)
            #pragma unroll
            for (int e = 0; e < 4; e++) {
                int gn = bm * 128 + wy * 32 + mi * 16 + gq + (e >> 1) * 8;
                int gc = bn * 128 + wx * 64 + ni * 8 + 2 * tq + (e & 1);
                int dd = gn / M, n = gn % M, mod = n >> 6, ii = n & 63;
                out[(size_t)(dd * L + ii) * 768 + mod * 256 + gc] =
                    fmaxf(acc[mi][ni][e] + bh[gc], 0.f);
            }
}

// ---------------- K7: norms, diag sims, zero LSE accumulators, bf16 convert ----------------
__global__ void k_norm(const float* out) {
    int i = blockIdx.x;
    int tid = threadIdx.x;
    float tv = out[(size_t)i * 768 + tid];
    float av = out[(size_t)i * 768 + 256 + tid];
    float vv = out[(size_t)i * 768 + 512 + tid];
    float q[6] = { tv * tv, av * av, vv * vv, tv * av, tv * vv, av * vv };
    __shared__ float red[6][8];
    __shared__ float sinv[3];
    int lane = tid & 31, w = tid >> 5;
    #pragma unroll
    for (int o = 16; o; o >>= 1)
        #pragma unroll
        for (int k = 0; k < 6; k++) q[k] += __shfl_down_sync(0xffffffffu, q[k], o);
    if (lane == 0)
        #pragma unroll
        for (int k = 0; k < 6; k++) red[k][w] = q[k];
    __syncthreads();
    if (tid == 0) {
        float s[6];
        #pragma unroll
        for (int k = 0; k < 6; k++) {
            s[k] = 0.f;
            #pragma unroll
            for (int w2 = 0; w2 < 8; w2++) s[k] += red[k][w2];
        }
        float it = 1.f / (sqrtf(s[0]) + 1e-8f);
        float ia = 1.f / (sqrtf(s[1]) + 1e-8f);
        float iv = 1.f / (sqrtf(s[2]) + 1e-8f);
        sinv[0] = it * SQTAUI; sinv[1] = ia * SQTAUI; sinv[2] = iv * SQTAUI;
        g_diag[i]             = s[3] * it * ia * TAUINV;
        g_diag[NROWS + i]     = s[4] * it * iv * TAUINV;
        g_diag[2 * NROWS + i] = s[5] * ia * iv * TAUINV;
        g_rowsum[i] = 0.f; g_rowsum[NROWS + i] = 0.f; g_rowsum[2 * NROWS + i] = 0.f;
        g_colsum[i] = 0.f; g_colsum[NROWS + i] = 0.f; g_colsum[2 * NROWS + i] = 0.f;
    }
    __syncthreads();
    g_nb[((size_t)0 * NROWS + i) * G + tid] = __float2bfloat16(tv * sinv[0]);
    g_nb[((size_t)1 * NROWS + i) * G + tid] = __float2bfloat16(av * sinv[1]);
    g_nb[((size_t)2 * NROWS + i) * G + tid] = __float2bfloat16(vv * sinv[2]);
}

// ---------------- K8: bf16 sim tiles; X panel resident, 4 col tiles per block ----------------
#define SPITCH 40
#define XPITCH 264
#define SIM_SMEM (128*XPITCH*2 + 2*128*SPITCH*2 + 256*4)
__global__ void __launch_bounds__(256) k_sim_mma() {
    extern __shared__ __align__(16) char dsm[];
    __nv_bfloat16* sXp = (__nv_bfloat16*)dsm;                       // 128 x 256 panel
    __nv_bfloat16* sY  = sXp + 128 * XPITCH;                         // 2 x 128 x SPITCH
    float* srow = (float*)(sY + 2 * 128 * SPITCH);
    float* scol = srow + 128;

    int p = blockIdx.z;
    int mx = (p == 2) ? 1 : 0;
    int my = (p == 0) ? 1 : 2;
    int row0 = blockIdx.y * 128;
    int tid = threadIdx.x, lane = tid & 31, warp = tid >> 5;
    int wy = warp >> 1, wx = warp & 1;      // warp tile: 32 rows x 64 cols

    const __nv_bfloat16* xg = g_nb + ((size_t)mx * NROWS + row0) * G;

    #pragma unroll
    for (int it = 0; it < 16; it++) {
        int idx = tid + it * 256;
        int r = idx >> 5, c = (idx & 31) * 8;
        cp16(sXp + r * XPITCH + c, xg + (size_t)r * G + c);
    }
    cp_commit();
    asm volatile("cp.async.wait_group 0;");
    __syncthreads();

    int lr = tid >> 2, lc = (tid & 3) * 8;
    int lr2 = lr + 64;

    for (int j = 0; j < 4; j++) {
        int col0 = (blockIdx.x * 4 + j) * 128;
        const __nv_bfloat16* yg = g_nb + ((size_t)my * NROWS + col0) * G;

        float acc[2][8][4];
        #pragma unroll
        for (int mi = 0; mi < 2; mi++)
            #pragma unroll
            for (int ni = 0; ni < 8; ni++)
                #pragma unroll
                for (int r = 0; r < 4; r++) acc[mi][ni][r] = 0.f;

        cp16(sY + lr * SPITCH + lc,  yg + (size_t)lr * G + lc);
        cp16(sY + lr2 * SPITCH + lc, yg + (size_t)lr2 * G + lc);
        cp_commit();

        #pragma unroll
        for (int c = 0; c < 8; c++) {
            int cur = c & 1;
            if (c < 7) {
                int nb = (c + 1) & 1, kc2 = (c + 1) * 32;
                cp16(sY + nb * 128 * SPITCH + lr * SPITCH + lc,
                     yg + (size_t)lr * G + kc2 + lc);
                cp16(sY + nb * 128 * SPITCH + lr2 * SPITCH + lc,
                     yg + (size_t)lr2 * G + kc2 + lc);
                cp_commit();
                asm volatile("cp.async.wait_group 1;");
            } else {
                asm volatile("cp.async.wait_group 0;");
            }
            __syncthreads();
            int kc = c * 32;
            #pragma unroll
            for (int ks = 0; ks < 2; ks++) {
                int k0 = ks * 16;
                unsigned A[2][4];
                #pragma unroll
                for (int mi = 0; mi < 2; mi++) {
                    int r = wy * 32 + mi * 16 + ((lane >> 3) & 1) * 8 + (lane & 7);
                    int cc = kc + k0 + (lane >> 4) * 8;
                    unsigned ad = (unsigned)__cvta_generic_to_shared(sXp + r * XPITCH + cc);
                    asm volatile("ldmatrix.sync.aligned.m8n8.x4.shared.b16 {%0,%1,%2,%3},[%4];"
                        : "=r"(A[mi][0]), "=r"(A[mi][1]), "=r"(A[mi][2]), "=r"(A[mi][3])
                        : "r"(ad));
                }
                unsigned B[8][2];
                #pragma unroll
                for (int nb2 = 0; nb2 < 4; nb2++) {
                    int r = wx * 64 + nb2 * 16 + (lane >> 4) * 8 + (lane & 7);
                    int cc = k0 + ((lane >> 3) & 1) * 8;
                    unsigned ad = (unsigned)__cvta_generic_to_shared(
                        sY + cur * 128 * SPITCH + r * SPITCH + cc);
                    asm volatile("ldmatrix.sync.aligned.m8n8.x4.shared.b16 {%0,%1,%2,%3},[%4];"
                        : "=r"(B[2 * nb2][0]), "=r"(B[2 * nb2][1]),
                          "=r"(B[2 * nb2 + 1][0]), "=r"(B[2 * nb2 + 1][1])
                        : "r"(ad));
                }
                #pragma unroll
                for (int mi = 0; mi < 2; mi++)
                    #pragma unroll
                    for (int ni = 0; ni < 8; ni++)
                        asm volatile(
                            "mma.sync.aligned.m16n8k16.row.col.f32.bf16.bf16.f32 "
                            "{%0,%1,%2,%3},{%4,%5,%6,%7},{%8,%9},{%0,%1,%2,%3};"
                            : "+f"(acc[mi][ni][0]), "+f"(acc[mi][ni][1]),
                              "+f"(acc[mi][ni][2]), "+f"(acc[mi][ni][3])
                            : "r"(A[mi][0]), "r"(A[mi][1]), "r"(A[mi][2]), "r"(A[mi][3]),
                              "r"(B[ni][0]), "r"(B[ni][1]));
            }
            __syncthreads();
        }

        if (tid < 128) { srow[tid] = 0.f; scol[tid] = 0.f; }
        __syncthreads();

        float rowp[2][2] = {{0.f, 0.f}, {0.f, 0.f}};
        float colp[8][2];
        #pragma unroll
        for (int ni = 0; ni < 8; ni++) { colp[ni][0] = 0.f; colp[ni][1] = 0.f; }
        #pragma unroll
        for (int mi = 0; mi < 2; mi++)
            #pragma unroll
            for (int ni = 0; ni < 8; ni++)
                #pragma unroll
                for (int r = 0; r < 4; r++) {
                    float e = __expf(acc[mi][ni][r]);
                    rowp[mi][r >> 1] += e;
                    colp[ni][r & 1] += e;
                }

        #pragma unroll
        for (int mi = 0; mi < 2; mi++)
            #pragma unroll
            for (int h = 0; h < 2; h++) {
                float vv = rowp[mi][h];
                vv += __shfl_xor_sync(0xffffffffu, vv, 1);
                vv += __shfl_xor_sync(0xffffffffu, vv, 2);
                if ((lane & 3) == 0)
                    atomicAdd(&srow[wy * 32 + mi * 16 + (lane >> 2) + h * 8], vv);
            }
        #pragma unroll
        for (int ni = 0; ni < 8; ni++)
            #pragma unroll
            for (int s2 = 0; s2 < 2; s2++) {
                float vv = colp[ni][s2];
                vv += __shfl_xor_sync(0xffffffffu, vv, 4);
                vv += __shfl_xor_sync(0xffffffffu, vv, 8);
                vv += __shfl_xor_sync(0xffffffffu, vv, 16);
                if (lane < 4)
                    atomicAdd(&scol[wx * 64 + ni * 8 + lane * 2 + s2], vv);
            }
        __syncthreads();
        if (tid < 128) {
            atomicAdd(&g_rowsum[p * NROWS + row0 + tid], srow[tid]);
            atomicAdd(&g_colsum[p * NROWS + col0 + tid], scol[tid]);
        }
        __syncthreads();
    }
}

// ---------------- K9: final loss reduction ----------------
__global__ void k_loss(float* out, int out_size) {
    int tid = threadIdx.x;
    float s = 0.f;
    for (int idx = tid; idx < 3 * NROWS; idx += 256) {
        float dg = g_diag[idx];
        s += 2.f * dg - logf(g_rowsum[idx]) - logf(g_colsum[idx]);
    }
    __shared__ float red[8];
    int lane = tid & 31, w = tid >> 5;
    #pragma unroll
    for (int o = 16; o; o >>= 1) s += __shfl_down_sync(0xffffffffu, s, o);
    if (lane == 0) red[w] = s;
    __syncthreads();
    if (tid == 0) {
        float tot = 0.f;
        #pragma unroll
        for (int w2 = 0; w2 < 8; w2++) tot += red[w2];
        float loss = -tot / (2.f * 3.f * (float)NROWS);
        if (out_size > NROWS * 768) out[NROWS * 768] = loss;
    }
}

// ---------------- launcher ----------------
extern "C" void kernel_launch(void* const* d_in, const int* in_sizes, int n_in,
                              void* d_out, int out_size) {
    const float* t   = (const float*)d_in[0];
    const float* a   = (const float*)d_in[1];
    const float* v   = (const float*)d_in[2];
    const float* Wfc = (const float*)d_in[3];
    const float* bfc = (const float*)d_in[4];
    const float* Wh  = (const float*)d_in[5];
    const float* bh  = (const float*)d_in[6];
    float* out = (float*)d_out;

    cudaFuncSetAttribute(k_sim_mma,
        cudaFuncAttributeMaxDynamicSharedMemorySize, SIM_SMEM);
    cudaFuncSetAttribute(k_agg_f,
        cudaFuncAttributeMaxDynamicSharedMemorySize, AGG_SMEM);
    cudaFuncSetAttribute(k_gram_mma,
        cudaFuncAttributeMaxDynamicSharedMemorySize, GRAM_SMEM);

    k_sq<<<NNODE / 8, 256>>>(t, a, v);
    k_gram_mma<<<dim3(6, 64), 256, GRAM_SMEM>>>();
    k_fc_mma<<<dim3(2, 96), 256>>>(Wfc, bfc);
    k_agg_f<<<dim3(4, 64), 256, AGG_SMEM>>>();
    k_out_mma<<<dim3(2, 96), 256>>>(Wh, bh, out);
    k_norm<<<NROWS, 256>>>(out);
    k_sim_mma<<<dim3(8, 32, 3), 256, SIM_SMEM>>>();
    k_loss<<<1, 256>>>(out, out_size);
}